// round 1
// baseline (speedup 1.0000x reference)
#include <cuda_runtime.h>
#include <math.h>

// Problem constants (B=2, S=2048 -> N=4096 tokens)
#define NTOK 4096
#define DDIM 1024
#define IDIM 2048
#define NEXP 8
#define TOPK 2
// routed rows padded to 64 per expert segment: 8192 + 8*64 headroom
#define MAXROWS 8704
#define NTILES 136   // MAXROWS / 64

// ---------------- scratch (device globals; no allocation allowed) ------------
__device__ float g_G[(size_t)MAXROWS * IDIM];   // intermediate silu(gate)*up, reused shared->routed
__device__ int   g_topk_idx[NTOK * TOPK];
__device__ float g_topk_w[NTOK * TOPK];
__device__ int   g_cnt[NEXP];
__device__ float g_Psum[NEXP];
__device__ int   g_cursor[NEXP];
__device__ int   g_off[NEXP + 1];
__device__ int   g_pair_token[MAXROWS];
__device__ float g_pair_w[MAXROWS];
__device__ int   g_tile_expert[NTILES];

// ---------------- init ----------------
__global__ void init_kernel() {
    int i = blockIdx.x * blockDim.x + threadIdx.x;
    if (i < NEXP) { g_cnt[i] = 0; g_Psum[i] = 0.f; g_cursor[i] = 0; }
    if (i < MAXROWS) { g_pair_token[i] = -1; g_pair_w[i] = 0.f; }
}

// ---------------- routing: one warp per token ----------------
__global__ void routing_kernel(const float* __restrict__ x,
                               const float* __restrict__ Wg) {
    int gwarp = (blockIdx.x * blockDim.x + threadIdx.x) >> 5;
    int lane  = threadIdx.x & 31;
    if (gwarp >= NTOK) return;
    const float* xr = x + (size_t)gwarp * DDIM;

    float acc[NEXP];
#pragma unroll
    for (int e = 0; e < NEXP; e++) acc[e] = 0.f;

    for (int j = lane; j < DDIM; j += 32) {
        float xv = xr[j];
        const float* wr = Wg + (size_t)j * NEXP;
#pragma unroll
        for (int e = 0; e < NEXP; e++) acc[e] = fmaf(xv, wr[e], acc[e]);
    }
#pragma unroll
    for (int e = 0; e < NEXP; e++) {
#pragma unroll
        for (int o = 16; o; o >>= 1) acc[e] += __shfl_xor_sync(0xffffffffu, acc[e], o);
    }
    // all lanes now hold all 8 logits
    float mx = acc[0];
#pragma unroll
    for (int e = 1; e < NEXP; e++) mx = fmaxf(mx, acc[e]);
    float p[NEXP], s = 0.f;
#pragma unroll
    for (int e = 0; e < NEXP; e++) { p[e] = expf(acc[e] - mx); s += p[e]; }
    float invs = 1.f / s;
#pragma unroll
    for (int e = 0; e < NEXP; e++) p[e] *= invs;

    if (lane < NEXP) atomicAdd(&g_Psum[lane], p[lane]);

    if (lane == 0) {
        // top-2, lowest index wins ties (strict >)
        int i0 = 0;
#pragma unroll
        for (int e = 1; e < NEXP; e++) if (p[e] > p[i0]) i0 = e;
        int i1 = (i0 == 0) ? 1 : 0;
#pragma unroll
        for (int e = 0; e < NEXP; e++) if (e != i0 && p[e] > p[i1]) i1 = e;
        float w0 = p[i0], w1 = p[i1];
        float inv = 1.f / (w0 + w1 + 1e-9f);
        g_topk_idx[gwarp * 2 + 0] = i0;
        g_topk_idx[gwarp * 2 + 1] = i1;
        g_topk_w[gwarp * 2 + 0] = w0 * inv;
        g_topk_w[gwarp * 2 + 1] = w1 * inv;
        atomicAdd(&g_cnt[i0], 1);
        atomicAdd(&g_cnt[i1], 1);
    }
}

// ---------------- offsets + aux loss (1 thread; tiny) ----------------
__global__ void offsets_kernel(float* __restrict__ out, int out_size) {
    g_off[0] = 0;
    for (int e = 0; e < NEXP; e++)
        g_off[e + 1] = g_off[e] + ((g_cnt[e] + 63) / 64) * 64;
    for (int t = 0; t < NTILES; t++) {
        int te = 0;
        int r = t * 64;
        for (int e = 0; e < NEXP; e++)
            if (r >= g_off[e] && r < g_off[e + 1]) te = e;
        g_tile_expert[t] = te;
    }
    float aux = 0.f;
    for (int e = 0; e < NEXP; e++) {
        float f = (float)g_cnt[e] / ((float)(NTOK * TOPK) + 1e-9f);
        float P = g_Psum[e] / (float)NTOK;
        aux += f * P;
    }
    out[out_size - 1] = 0.01f * (float)NEXP * aux;
}

// ---------------- scatter (token, weight) pairs into expert segments ---------
__global__ void scatter_kernel() {
    int n = blockIdx.x * blockDim.x + threadIdx.x;
    if (n >= NTOK) return;
#pragma unroll
    for (int k = 0; k < TOPK; k++) {
        int e = g_topk_idx[n * 2 + k];
        int slot = g_off[e] + atomicAdd(&g_cursor[e], 1);
        g_pair_token[slot] = n;
        g_pair_w[slot] = g_topk_w[n * 2 + k];
    }
}

// ---------------- fused up/gate GEMM + SiLU ----------------
// C1 = X@W1, C2 = X@W2, G = silu(C1)*C2   (X rows gathered for routed path)
// Block: 64(M) x 64(N), BK=16, 256 threads, 4x4 micro-tile, two outputs.
template <bool ROUTED>
__global__ void __launch_bounds__(256, 2)
upgate_kernel(const float* __restrict__ X,
              const float* __restrict__ W1base,
              const float* __restrict__ W2base) {
    __shared__ __align__(16) float As[16 * 64];
    __shared__ __align__(16) float B1s[16 * 64];
    __shared__ __align__(16) float B2s[16 * 64];

    int tid = threadIdx.x;
    int tx = tid & 15, ty = tid >> 4;
    int m0 = blockIdx.y * 64, n0 = blockIdx.x * 64;

    const float* w1 = W1base;
    const float* w2 = W2base;
    if (ROUTED) {
        int e = g_tile_expert[blockIdx.y];
        size_t off = (size_t)e * DDIM * IDIM;
        w1 += off; w2 += off;
    }

    int arow = tid >> 2, akq = tid & 3;  // A loader: row in tile, k-quad
    int tok;
    if (ROUTED) tok = g_pair_token[m0 + arow];
    else        tok = m0 + arow;
    const float4* Xrow = (tok >= 0) ? (const float4*)(X + (size_t)tok * DDIM) : nullptr;

    int brow = tid >> 4, bcol = tid & 15;  // B loader

    float c1[4][4], c2[4][4];
#pragma unroll
    for (int i = 0; i < 4; i++)
#pragma unroll
        for (int j = 0; j < 4; j++) { c1[i][j] = 0.f; c2[i][j] = 0.f; }

    for (int k0 = 0; k0 < DDIM; k0 += 16) {
        float4 av = Xrow ? Xrow[(k0 >> 2) + akq] : make_float4(0.f, 0.f, 0.f, 0.f);
        As[(akq * 4 + 0) * 64 + arow] = av.x;
        As[(akq * 4 + 1) * 64 + arow] = av.y;
        As[(akq * 4 + 2) * 64 + arow] = av.z;
        As[(akq * 4 + 3) * 64 + arow] = av.w;
        const float* b1p = w1 + (size_t)(k0 + brow) * IDIM + n0 + bcol * 4;
        const float* b2p = w2 + (size_t)(k0 + brow) * IDIM + n0 + bcol * 4;
        ((float4*)B1s)[brow * 16 + bcol] = *(const float4*)b1p;
        ((float4*)B2s)[brow * 16 + bcol] = *(const float4*)b2p;
        __syncthreads();

#pragma unroll
        for (int k = 0; k < 16; k++) {
            float4 a4  = ((const float4*)As)[k * 16 + ty];
            float4 b14 = ((const float4*)B1s)[k * 16 + tx];
            float4 b24 = ((const float4*)B2s)[k * 16 + tx];
            float a[4]  = {a4.x, a4.y, a4.z, a4.w};
            float b1[4] = {b14.x, b14.y, b14.z, b14.w};
            float b2[4] = {b24.x, b24.y, b24.z, b24.w};
#pragma unroll
            for (int i = 0; i < 4; i++)
#pragma unroll
                for (int j = 0; j < 4; j++) {
                    c1[i][j] = fmaf(a[i], b1[j], c1[i][j]);
                    c2[i][j] = fmaf(a[i], b2[j], c2[i][j]);
                }
        }
        __syncthreads();
    }

#pragma unroll
    for (int i = 0; i < 4; i++) {
        int r = m0 + ty * 4 + i;
        float4 o;
        float g0 = c1[i][0], g1 = c1[i][1], g2 = c1[i][2], g3 = c1[i][3];
        o.x = (g0 / (1.f + expf(-g0))) * c2[i][0];
        o.y = (g1 / (1.f + expf(-g1))) * c2[i][1];
        o.z = (g2 / (1.f + expf(-g2))) * c2[i][2];
        o.w = (g3 / (1.f + expf(-g3))) * c2[i][3];
        *(float4*)(g_G + (size_t)r * IDIM + n0 + tx * 4) = o;
    }
}

// ---------------- down GEMM ----------------
// shared: out = G @ Wd (direct store; initializes d_out)
// routed: out[token] += weight * (G @ W_down[e]) via atomicAdd
template <bool ROUTED>
__global__ void __launch_bounds__(256, 2)
down_kernel(const float* __restrict__ Wdbase, float* __restrict__ out) {
    __shared__ __align__(16) float As[16 * 64];
    __shared__ __align__(16) float Bs[16 * 64];

    int tid = threadIdx.x;
    int tx = tid & 15, ty = tid >> 4;
    int m0 = blockIdx.y * 64, n0 = blockIdx.x * 64;

    const float* w = Wdbase;
    if (ROUTED) w += (size_t)g_tile_expert[blockIdx.y] * IDIM * DDIM;

    int arow = tid >> 2, akq = tid & 3;
    const float4* Grow = (const float4*)(g_G + (size_t)(m0 + arow) * IDIM);
    int brow = tid >> 4, bcol = tid & 15;

    float c[4][4];
#pragma unroll
    for (int i = 0; i < 4; i++)
#pragma unroll
        for (int j = 0; j < 4; j++) c[i][j] = 0.f;

    for (int k0 = 0; k0 < IDIM; k0 += 16) {
        float4 av = Grow[(k0 >> 2) + akq];
        As[(akq * 4 + 0) * 64 + arow] = av.x;
        As[(akq * 4 + 1) * 64 + arow] = av.y;
        As[(akq * 4 + 2) * 64 + arow] = av.z;
        As[(akq * 4 + 3) * 64 + arow] = av.w;
        const float* bp = w + (size_t)(k0 + brow) * DDIM + n0 + bcol * 4;
        ((float4*)Bs)[brow * 16 + bcol] = *(const float4*)bp;
        __syncthreads();

#pragma unroll
        for (int k = 0; k < 16; k++) {
            float4 a4 = ((const float4*)As)[k * 16 + ty];
            float4 b4 = ((const float4*)Bs)[k * 16 + tx];
            float a[4] = {a4.x, a4.y, a4.z, a4.w};
            float b[4] = {b4.x, b4.y, b4.z, b4.w};
#pragma unroll
            for (int i = 0; i < 4; i++)
#pragma unroll
                for (int j = 0; j < 4; j++)
                    c[i][j] = fmaf(a[i], b[j], c[i][j]);
        }
        __syncthreads();
    }

    if (!ROUTED) {
#pragma unroll
        for (int i = 0; i < 4; i++) {
            int r = m0 + ty * 4 + i;
            float4 o = make_float4(c[i][0], c[i][1], c[i][2], c[i][3]);
            *(float4*)(out + (size_t)r * DDIM + n0 + tx * 4) = o;
        }
    } else {
#pragma unroll
        for (int i = 0; i < 4; i++) {
            int r = m0 + ty * 4 + i;
            int t = g_pair_token[r];
            if (t < 0) continue;
            float wgt = g_pair_w[r];
            float* op = out + (size_t)t * DDIM + n0 + tx * 4;
            atomicAdd(op + 0, wgt * c[i][0]);
            atomicAdd(op + 1, wgt * c[i][1]);
            atomicAdd(op + 2, wgt * c[i][2]);
            atomicAdd(op + 3, wgt * c[i][3]);
        }
    }
}

// ---------------- launch ----------------
extern "C" void kernel_launch(void* const* d_in, const int* in_sizes, int n_in,
                              void* d_out, int out_size) {
    const float* x        = (const float*)d_in[0];
    const float* Wg       = (const float*)d_in[1];
    const float* W_gate   = (const float*)d_in[2];
    const float* W_up     = (const float*)d_in[3];
    const float* W_down   = (const float*)d_in[4];
    const float* Ws_gate  = (const float*)d_in[5];
    const float* Ws_up    = (const float*)d_in[6];
    const float* Ws_down  = (const float*)d_in[7];
    float* out = (float*)d_out;

    init_kernel<<<(MAXROWS + 255) / 256, 256>>>();
    routing_kernel<<<(NTOK * 32 + 255) / 256, 256>>>(x, Wg);
    offsets_kernel<<<1, 1>>>(out, out_size);
    scatter_kernel<<<(NTOK + 255) / 256, 256>>>();

    // shared expert: fills g_G[0..NTOK), then writes d_out (initializes it)
    upgate_kernel<false><<<dim3(IDIM / 64, NTOK / 64), 256>>>(x, Ws_gate, Ws_up);
    down_kernel<false><<<dim3(DDIM / 64, NTOK / 64), 256>>>(Ws_down, out);

    // routed experts: padded grouped GEMM over expert-sorted rows
    upgate_kernel<true><<<dim3(IDIM / 64, NTILES), 256>>>(x, W_gate, W_up);
    down_kernel<true><<<dim3(DDIM / 64, NTILES), 256>>>(W_down, out);
}

// round 3
// speedup vs baseline: 2.1343x; 2.1343x over previous
#include <cuda_runtime.h>
#include <cuda_bf16.h>
#include <math.h>
#include <stdint.h>

// Problem constants (B=2, S=2048 -> N=4096 tokens)
#define NTOK 4096
#define DDIM 1024
#define IDIM 2048
#define NEXP 8
#define TOPK 2
#define BM   128
// routed rows padded to 128 per expert segment: 8192 + 8*128
#define MAXROWS 9216
#define NTILES  72

// ---------------- scratch (device globals) ----------------
__device__ __align__(16) float g_G[(size_t)MAXROWS * IDIM];
__device__ int   g_topk_idx[NTOK * TOPK];
__device__ float g_topk_w[NTOK * TOPK];
__device__ int   g_cnt[NEXP];
__device__ float g_Psum[NEXP];
__device__ int   g_cursor[NEXP];
__device__ int   g_off[NEXP + 1];
__device__ int   g_pair_token[MAXROWS];
__device__ float g_pair_w[MAXROWS];
__device__ int   g_tile_expert[NTILES];

// ---------------- helpers ----------------
__device__ __forceinline__ uint32_t smem_u32(const void* p) {
    uint32_t a;
    asm("{ .reg .u64 t; cvta.to.shared.u64 t, %1; cvt.u32.u64 %0, t; }" : "=r"(a) : "l"(p));
    return a;
}
__device__ __forceinline__ void ldsm_x4(uint32_t* r, uint32_t addr) {
    asm volatile("ldmatrix.sync.aligned.m8n8.x4.shared.b16 {%0,%1,%2,%3}, [%4];"
                 : "=r"(r[0]), "=r"(r[1]), "=r"(r[2]), "=r"(r[3]) : "r"(addr));
}
__device__ __forceinline__ void ldsm_x4_t(uint32_t* r, uint32_t addr) {
    asm volatile("ldmatrix.sync.aligned.m8n8.x4.trans.shared.b16 {%0,%1,%2,%3}, [%4];"
                 : "=r"(r[0]), "=r"(r[1]), "=r"(r[2]), "=r"(r[3]) : "r"(addr));
}
__device__ __forceinline__ void mma16816(float* c, const uint32_t* a, const uint32_t* b) {
    asm volatile("mma.sync.aligned.m16n8k16.row.col.f32.bf16.bf16.f32 "
                 "{%0,%1,%2,%3}, {%4,%5,%6,%7}, {%8,%9}, {%0,%1,%2,%3};"
                 : "+f"(c[0]), "+f"(c[1]), "+f"(c[2]), "+f"(c[3])
                 : "r"(a[0]), "r"(a[1]), "r"(a[2]), "r"(a[3]), "r"(b[0]), "r"(b[1]));
}
// split two fp32 into bf16 hi pair + bf16 lo (residual) pair
__device__ __forceinline__ void split2(float x, float y, uint32_t& hi, uint32_t& lo) {
    __nv_bfloat162 h = __floats2bfloat162_rn(x, y);
    float hx = __bfloat162float(__low2bfloat16(h));
    float hy = __bfloat162float(__high2bfloat16(h));
    __nv_bfloat162 l = __floats2bfloat162_rn(x - hx, y - hy);
    hi = *reinterpret_cast<uint32_t*>(&h);
    lo = *reinterpret_cast<uint32_t*>(&l);
}
__device__ __forceinline__ void split_sts4(char* bhi, char* blo, uint32_t off, float4 v) {
    uint2 hv, lv;
    split2(v.x, v.y, hv.x, lv.x);
    split2(v.z, v.w, hv.y, lv.y);
    *reinterpret_cast<uint2*>(bhi + off) = hv;
    *reinterpret_cast<uint2*>(blo + off) = lv;
}

// ---------------- small kernels ----------------
__global__ void init_kernel() {
    int i = blockIdx.x * blockDim.x + threadIdx.x;
    if (i < NEXP) { g_cnt[i] = 0; g_Psum[i] = 0.f; g_cursor[i] = 0; }
    if (i < MAXROWS) { g_pair_token[i] = -1; g_pair_w[i] = 0.f; }
}

__global__ void routing_kernel(const float* __restrict__ x, const float* __restrict__ Wg) {
    int gwarp = (blockIdx.x * blockDim.x + threadIdx.x) >> 5;
    int lane = threadIdx.x & 31;
    if (gwarp >= NTOK) return;
    const float* xr = x + (size_t)gwarp * DDIM;
    float acc[NEXP];
#pragma unroll
    for (int e = 0; e < NEXP; e++) acc[e] = 0.f;
    for (int j = lane; j < DDIM; j += 32) {
        float xv = xr[j];
        const float* wr = Wg + (size_t)j * NEXP;
#pragma unroll
        for (int e = 0; e < NEXP; e++) acc[e] = fmaf(xv, wr[e], acc[e]);
    }
#pragma unroll
    for (int e = 0; e < NEXP; e++) {
#pragma unroll
        for (int o = 16; o; o >>= 1) acc[e] += __shfl_xor_sync(0xffffffffu, acc[e], o);
    }
    float mx = acc[0];
#pragma unroll
    for (int e = 1; e < NEXP; e++) mx = fmaxf(mx, acc[e]);
    float p[NEXP], s = 0.f;
#pragma unroll
    for (int e = 0; e < NEXP; e++) { p[e] = expf(acc[e] - mx); s += p[e]; }
    float invs = 1.f / s;
#pragma unroll
    for (int e = 0; e < NEXP; e++) p[e] *= invs;
    if (lane < NEXP) atomicAdd(&g_Psum[lane], p[lane]);
    if (lane == 0) {
        int i0 = 0;
#pragma unroll
        for (int e = 1; e < NEXP; e++) if (p[e] > p[i0]) i0 = e;
        int i1 = (i0 == 0) ? 1 : 0;
#pragma unroll
        for (int e = 0; e < NEXP; e++) if (e != i0 && p[e] > p[i1]) i1 = e;
        float w0 = p[i0], w1 = p[i1];
        float inv = 1.f / (w0 + w1 + 1e-9f);
        g_topk_idx[gwarp * 2 + 0] = i0;
        g_topk_idx[gwarp * 2 + 1] = i1;
        g_topk_w[gwarp * 2 + 0] = w0 * inv;
        g_topk_w[gwarp * 2 + 1] = w1 * inv;
        atomicAdd(&g_cnt[i0], 1);
        atomicAdd(&g_cnt[i1], 1);
    }
}

__global__ void offsets_kernel(float* __restrict__ out, int out_size) {
    g_off[0] = 0;
    for (int e = 0; e < NEXP; e++)
        g_off[e + 1] = g_off[e] + ((g_cnt[e] + BM - 1) / BM) * BM;
    for (int t = 0; t < NTILES; t++) {
        int te = 0, r = t * BM;
        for (int e = 0; e < NEXP; e++)
            if (r >= g_off[e] && r < g_off[e + 1]) te = e;
        g_tile_expert[t] = te;
    }
    float aux = 0.f;
    for (int e = 0; e < NEXP; e++) {
        float f = (float)g_cnt[e] / ((float)(NTOK * TOPK) + 1e-9f);
        float P = g_Psum[e] / (float)NTOK;
        aux += f * P;
    }
    out[out_size - 1] = 0.01f * (float)NEXP * aux;
}

__global__ void scatter_kernel() {
    int n = blockIdx.x * blockDim.x + threadIdx.x;
    if (n >= NTOK) return;
#pragma unroll
    for (int k = 0; k < TOPK; k++) {
        int e = g_topk_idx[n * 2 + k];
        int slot = g_off[e] + atomicAdd(&g_cursor[e], 1);
        g_pair_token[slot] = n;
        g_pair_w[slot] = g_topk_w[n * 2 + k];
    }
}

// ---------------- SMEM layout constants ----------------
// A tile: 128 rows x 32 k bf16, row stride 80B (conflict-free ldmatrix)
// upgate B tiles: 32 k x 64 n bf16, row stride 144B; down B: 32 x 128, stride 272B
#define A_STRIDE 80
#define A_BYTES  (128 * A_STRIDE)          // 10240
#define UG_BSTRIDE 144
#define UG_BBYTES  (32 * UG_BSTRIDE)       // 4608
#define DN_BSTRIDE 272
#define DN_BBYTES  (32 * DN_BSTRIDE)       // 8704

#define UG_AHI 0
#define UG_ALO A_BYTES
#define UG_BGH (2 * A_BYTES)
#define UG_BGL (UG_BGH + UG_BBYTES)
#define UG_BUH (UG_BGL + UG_BBYTES)
#define UG_BUL (UG_BUH + UG_BBYTES)
#define UG_STAGE (UG_BUL + UG_BBYTES)      // 38912
#define UG_SMEM (2 * UG_STAGE)             // 77824

#define DN_AHI 0
#define DN_ALO A_BYTES
#define DN_BH  (2 * A_BYTES)
#define DN_BL  (DN_BH + DN_BBYTES)
#define DN_STAGE (DN_BL + DN_BBYTES)       // 37888
#define DN_SMEM (2 * DN_STAGE)             // 75776

// ---------------- fused up/gate GEMM (mma.sync bf16 split) + SiLU ----------------
// CTA tile: 128 M x 64 N. Warps 0-3 compute gate (X@W1), warps 4-7 up (X@W2).
// Warp tile 32x64. G = silu(gate)*up -> g_G (fp32).
template <bool ROUTED>
__global__ void __launch_bounds__(256)
upgate_mma(const float* __restrict__ X,
           const float* __restrict__ W1base,
           const float* __restrict__ W2base) {
    extern __shared__ char smem[];
    uint32_t sb = smem_u32(smem);
    int tid = threadIdx.x;
    int wid = tid >> 5, lane = tid & 31;
    int m0 = blockIdx.y * BM, n0 = blockIdx.x * 64;

    const float* w1 = W1base;
    const float* w2 = W2base;
    if (ROUTED) {
        size_t off = (size_t)g_tile_expert[blockIdx.y] * DDIM * IDIM;
        w1 += off; w2 += off;
    }

    // loader indices
    int ar = tid >> 1, ak = (tid & 1) * 16;             // A: 2 thr/row, 16 k each
    int tok = ROUTED ? g_pair_token[m0 + ar] : (m0 + ar);
    const float4* Xr = (tok >= 0) ? (const float4*)(X + (size_t)tok * DDIM) : nullptr;
    int bk = tid >> 3, bn = (tid & 7) * 8;              // B: 8 thr/k-row, 8 n each

    // ldmatrix lane addressing
    int arow_l = (lane & 7) + ((lane >> 3) & 1) * 8;    // 0..15
    int akc_l  = (lane >> 4) * 8;                       // 0/8
    int bkr_l  = arow_l;
    int bnc_l  = akc_l;
    int mw = (wid & 3) * 32;                            // warp row base
    bool isGate = (wid < 4);
    uint32_t bBaseH = isGate ? UG_BGH : UG_BUH;
    uint32_t bBaseL = isGate ? UG_BGL : UG_BUL;

    float acc[2][8][4];
#pragma unroll
    for (int i = 0; i < 2; i++)
#pragma unroll
        for (int j = 0; j < 8; j++)
#pragma unroll
            for (int q = 0; q < 4; q++) acc[i][j][q] = 0.f;

    const float4 z4 = make_float4(0.f, 0.f, 0.f, 0.f);
    float4 rA[4], rB1[2], rB2[2];

    // prologue: load + store stage 0
#pragma unroll
    for (int j = 0; j < 4; j++) rA[j] = Xr ? Xr[(ak >> 2) + j] : z4;
    {
        const float4* p1 = (const float4*)(w1 + (size_t)bk * IDIM + n0 + bn);
        const float4* p2 = (const float4*)(w2 + (size_t)bk * IDIM + n0 + bn);
        rB1[0] = p1[0]; rB1[1] = p1[1];
        rB2[0] = p2[0]; rB2[1] = p2[1];
    }
    char* st0 = smem;
#pragma unroll
    for (int j = 0; j < 4; j++)
        split_sts4(st0 + UG_AHI, st0 + UG_ALO, ar * A_STRIDE + (ak + j * 4) * 2, rA[j]);
    {
        uint32_t o = bk * UG_BSTRIDE + bn * 2;
        split_sts4(st0 + UG_BGH, st0 + UG_BGL, o, rB1[0]);
        split_sts4(st0 + UG_BGH, st0 + UG_BGL, o + 8, rB1[1]);
        split_sts4(st0 + UG_BUH, st0 + UG_BUL, o, rB2[0]);
        split_sts4(st0 + UG_BUH, st0 + UG_BUL, o + 8, rB2[1]);
    }
    __syncthreads();

    const int NST = DDIM / 32;  // 32
    for (int s = 0; s < NST; s++) {
        if (s + 1 < NST) {
            int k0 = (s + 1) * 32;
#pragma unroll
            for (int j = 0; j < 4; j++) rA[j] = Xr ? Xr[((k0 + ak) >> 2) + j] : z4;
            const float4* p1 = (const float4*)(w1 + (size_t)(k0 + bk) * IDIM + n0 + bn);
            const float4* p2 = (const float4*)(w2 + (size_t)(k0 + bk) * IDIM + n0 + bn);
            rB1[0] = p1[0]; rB1[1] = p1[1];
            rB2[0] = p2[0]; rB2[1] = p2[1];
        }
        uint32_t stg = sb + (uint32_t)((s & 1) * UG_STAGE);
#pragma unroll
        for (int ks = 0; ks < 32; ks += 16) {
            uint32_t aH[2][4], aL[2][4];
#pragma unroll
            for (int mt = 0; mt < 2; mt++) {
                uint32_t ao = (mw + mt * 16 + arow_l) * A_STRIDE + (ks + akc_l) * 2;
                ldsm_x4(aH[mt], stg + UG_AHI + ao);
                ldsm_x4(aL[mt], stg + UG_ALO + ao);
            }
#pragma unroll
            for (int g = 0; g < 4; g++) {
                uint32_t bo = (ks + bkr_l) * UG_BSTRIDE + (g * 16 + bnc_l) * 2;
                uint32_t bH[4], bL[4];
                ldsm_x4_t(bH, stg + bBaseH + bo);
                ldsm_x4_t(bL, stg + bBaseL + bo);
#pragma unroll
                for (int mt = 0; mt < 2; mt++)
#pragma unroll
                    for (int sub = 0; sub < 2; sub++) {
                        float* c = acc[mt][g * 2 + sub];
                        mma16816(c, aH[mt], bH + sub * 2);
                        mma16816(c, aH[mt], bL + sub * 2);
                        mma16816(c, aL[mt], bH + sub * 2);
                    }
            }
        }
        if (s + 1 < NST) {
            char* stn = smem + ((s + 1) & 1) * UG_STAGE;
#pragma unroll
            for (int j = 0; j < 4; j++)
                split_sts4(stn + UG_AHI, stn + UG_ALO, ar * A_STRIDE + (ak + j * 4) * 2, rA[j]);
            uint32_t o = bk * UG_BSTRIDE + bn * 2;
            split_sts4(stn + UG_BGH, stn + UG_BGL, o, rB1[0]);
            split_sts4(stn + UG_BGH, stn + UG_BGL, o + 8, rB1[1]);
            split_sts4(stn + UG_BUH, stn + UG_BUL, o, rB2[0]);
            split_sts4(stn + UG_BUH, stn + UG_BUL, o + 8, rB2[1]);
            __syncthreads();
        }
    }
    __syncthreads();

    // epilogue: up warps deposit C_up into exch (stage0 region, 128x64 fp32)
    float* exch = (float*)smem;
    int fr = lane >> 2, fc = (lane & 3) * 2;
    if (!isGate) {
#pragma unroll
        for (int mt = 0; mt < 2; mt++)
#pragma unroll
            for (int j = 0; j < 8; j++) {
                float* c = acc[mt][j];
                int r = mw + mt * 16 + fr, cl = j * 8 + fc;
                *(float2*)&exch[r * 64 + cl] = make_float2(c[0], c[1]);
                *(float2*)&exch[(r + 8) * 64 + cl] = make_float2(c[2], c[3]);
            }
    }
    __syncthreads();
    if (isGate) {
#pragma unroll
        for (int mt = 0; mt < 2; mt++)
#pragma unroll
            for (int j = 0; j < 8; j++) {
                float* c = acc[mt][j];
                int r = mw + mt * 16 + fr, cl = j * 8 + fc;
                float2 u0 = *(float2*)&exch[r * 64 + cl];
                float2 u1 = *(float2*)&exch[(r + 8) * 64 + cl];
                float2 g0, g1;
                g0.x = c[0] / (1.f + __expf(-c[0])) * u0.x;
                g0.y = c[1] / (1.f + __expf(-c[1])) * u0.y;
                g1.x = c[2] / (1.f + __expf(-c[2])) * u1.x;
                g1.y = c[3] / (1.f + __expf(-c[3])) * u1.y;
                *(float2*)&exch[r * 64 + cl] = g0;
                *(float2*)&exch[(r + 8) * 64 + cl] = g1;
            }
    }
    __syncthreads();
    // coalesced copy exch -> g_G
    {
        int r = tid >> 1, cb = (tid & 1) * 32;
        float* dst = g_G + (size_t)(m0 + r) * IDIM + n0 + cb;
        const float4* src = (const float4*)&exch[r * 64 + cb];
#pragma unroll
        for (int j = 0; j < 8; j++) ((float4*)dst)[j] = src[j];
    }
}

// ---------------- down GEMM (mma.sync bf16 split) ----------------
// CTA tile 128 M x 128 N; warps 4x2, warp tile 32x64.
template <bool ROUTED>
__global__ void __launch_bounds__(256)
down_mma(const float* __restrict__ Wdbase, float* __restrict__ out) {
    extern __shared__ char smem[];
    uint32_t sb = smem_u32(smem);
    int tid = threadIdx.x;
    int wid = tid >> 5, lane = tid & 31;
    int m0 = blockIdx.y * BM, n0 = blockIdx.x * 128;

    const float* w = Wdbase;
    if (ROUTED) w += (size_t)g_tile_expert[blockIdx.y] * IDIM * DDIM;

    int ar = tid >> 1, ak = (tid & 1) * 16;
    const float4* Gr = (const float4*)(g_G + (size_t)(m0 + ar) * IDIM);
    int bk = tid >> 3, bn = (tid & 7) * 16;

    int arow_l = (lane & 7) + ((lane >> 3) & 1) * 8;
    int akc_l = (lane >> 4) * 8;
    int mw = (wid >> 1) * 32;
    int nwo = (wid & 1) * 64;

    float acc[2][8][4];
#pragma unroll
    for (int i = 0; i < 2; i++)
#pragma unroll
        for (int j = 0; j < 8; j++)
#pragma unroll
            for (int q = 0; q < 4; q++) acc[i][j][q] = 0.f;

    float4 rA[4], rB[4];
#pragma unroll
    for (int j = 0; j < 4; j++) rA[j] = Gr[(ak >> 2) + j];
    {
        const float4* p = (const float4*)(w + (size_t)bk * DDIM + n0 + bn);
#pragma unroll
        for (int j = 0; j < 4; j++) rB[j] = p[j];
    }
    char* st0 = smem;
#pragma unroll
    for (int j = 0; j < 4; j++)
        split_sts4(st0 + DN_AHI, st0 + DN_ALO, ar * A_STRIDE + (ak + j * 4) * 2, rA[j]);
#pragma unroll
    for (int j = 0; j < 4; j++)
        split_sts4(st0 + DN_BH, st0 + DN_BL, bk * DN_BSTRIDE + (bn + j * 4) * 2, rB[j]);
    __syncthreads();

    const int NST = IDIM / 32;  // 64
    for (int s = 0; s < NST; s++) {
        if (s + 1 < NST) {
            int k0 = (s + 1) * 32;
#pragma unroll
            for (int j = 0; j < 4; j++) rA[j] = Gr[((k0 + ak) >> 2) + j];
            const float4* p = (const float4*)(w + (size_t)(k0 + bk) * DDIM + n0 + bn);
#pragma unroll
            for (int j = 0; j < 4; j++) rB[j] = p[j];
        }
        uint32_t stg = sb + (uint32_t)((s & 1) * DN_STAGE);
#pragma unroll
        for (int ks = 0; ks < 32; ks += 16) {
            uint32_t aH[2][4], aL[2][4];
#pragma unroll
            for (int mt = 0; mt < 2; mt++) {
                uint32_t ao = (mw + mt * 16 + arow_l) * A_STRIDE + (ks + akc_l) * 2;
                ldsm_x4(aH[mt], stg + DN_AHI + ao);
                ldsm_x4(aL[mt], stg + DN_ALO + ao);
            }
#pragma unroll
            for (int g = 0; g < 4; g++) {
                uint32_t bo = (ks + arow_l) * DN_BSTRIDE + (nwo + g * 16 + akc_l) * 2;
                uint32_t bH[4], bL[4];
                ldsm_x4_t(bH, stg + DN_BH + bo);
                ldsm_x4_t(bL, stg + DN_BL + bo);
#pragma unroll
                for (int mt = 0; mt < 2; mt++)
#pragma unroll
                    for (int sub = 0; sub < 2; sub++) {
                        float* c = acc[mt][g * 2 + sub];
                        mma16816(c, aH[mt], bH + sub * 2);
                        mma16816(c, aH[mt], bL + sub * 2);
                        mma16816(c, aL[mt], bH + sub * 2);
                    }
            }
        }
        if (s + 1 < NST) {
            char* stn = smem + ((s + 1) & 1) * DN_STAGE;
#pragma unroll
            for (int j = 0; j < 4; j++)
                split_sts4(stn + DN_AHI, stn + DN_ALO, ar * A_STRIDE + (ak + j * 4) * 2, rA[j]);
#pragma unroll
            for (int j = 0; j < 4; j++)
                split_sts4(stn + DN_BH, stn + DN_BL, bk * DN_BSTRIDE + (bn + j * 4) * 2, rB[j]);
            __syncthreads();
        }
    }
    __syncthreads();  // all MMA done before C staging overwrites buffers

    // stage C (128x128 fp32) in smem for coalesced output
    float* Cs = (float*)smem;
    int fr = lane >> 2, fc = (lane & 3) * 2;
#pragma unroll
    for (int mt = 0; mt < 2; mt++)
#pragma unroll
        for (int j = 0; j < 8; j++) {
            float* c = acc[mt][j];
            int r = mw + mt * 16 + fr, cl = nwo + j * 8 + fc;
            *(float2*)&Cs[r * 128 + cl] = make_float2(c[0], c[1]);
            *(float2*)&Cs[(r + 8) * 128 + cl] = make_float2(c[2], c[3]);
        }
    __syncthreads();

    int r = tid >> 1, cb = (tid & 1) * 64;
    if (!ROUTED) {
        float* dst = out + (size_t)(m0 + r) * DDIM + n0 + cb;
#pragma unroll
        for (int j = 0; j < 16; j++)
            ((float4*)dst)[j] = ((const float4*)&Cs[r * 128 + cb])[j];
    } else {
        int tokr = g_pair_token[m0 + r];
        if (tokr >= 0) {
            float wgt = g_pair_w[m0 + r];
            float* dst = out + (size_t)tokr * DDIM + n0 + cb;
            const float* src = &Cs[r * 128 + cb];
#pragma unroll
            for (int j = 0; j < 64; j++)
                atomicAdd(dst + j, wgt * src[j]);
        }
    }
}

// ---------------- launch ----------------
extern "C" void kernel_launch(void* const* d_in, const int* in_sizes, int n_in,
                              void* d_out, int out_size) {
    const float* x       = (const float*)d_in[0];
    const float* Wg      = (const float*)d_in[1];
    const float* W_gate  = (const float*)d_in[2];
    const float* W_up    = (const float*)d_in[3];
    const float* W_down  = (const float*)d_in[4];
    const float* Ws_gate = (const float*)d_in[5];
    const float* Ws_up   = (const float*)d_in[6];
    const float* Ws_down = (const float*)d_in[7];
    float* out = (float*)d_out;

    cudaFuncSetAttribute(upgate_mma<false>, cudaFuncAttributeMaxDynamicSharedMemorySize, UG_SMEM);
    cudaFuncSetAttribute(upgate_mma<true>,  cudaFuncAttributeMaxDynamicSharedMemorySize, UG_SMEM);
    cudaFuncSetAttribute(down_mma<false>,   cudaFuncAttributeMaxDynamicSharedMemorySize, DN_SMEM);
    cudaFuncSetAttribute(down_mma<true>,    cudaFuncAttributeMaxDynamicSharedMemorySize, DN_SMEM);

    init_kernel<<<(MAXROWS + 255) / 256, 256>>>();
    routing_kernel<<<(NTOK * 32 + 255) / 256, 256>>>(x, Wg);
    offsets_kernel<<<1, 1>>>(out, out_size);
    scatter_kernel<<<(NTOK + 255) / 256, 256>>>();

    // shared expert
    upgate_mma<false><<<dim3(IDIM / 64, NTOK / BM), 256, UG_SMEM>>>(x, Ws_gate, Ws_up);
    down_mma<false><<<dim3(DDIM / 128, NTOK / BM), 256, DN_SMEM>>>(Ws_down, out);

    // routed experts (expert-sorted, 128-padded segments)
    upgate_mma<true><<<dim3(IDIM / 64, NTILES), 256, UG_SMEM>>>(x, W_gate, W_up);
    down_mma<true><<<dim3(DDIM / 128, NTILES), 256, DN_SMEM>>>(W_down, out);
}

// round 4
// speedup vs baseline: 2.2432x; 1.0510x over previous
#include <cuda_runtime.h>
#include <cuda_bf16.h>
#include <math.h>
#include <stdint.h>

// Problem constants (B=2, S=2048 -> N=4096 tokens)
#define NTOK 4096
#define DDIM 1024
#define IDIM 2048
#define NEXP 8
#define TOPK 2
#define BM   128
#define MAXROWS 9216
#define NTILES  72

// ---------------- scratch (device globals) ----------------
// pre-split bf16 hi/lo copies. expert index 8 = shared expert.
__device__ __align__(16) __nv_bfloat16 g_W1h[(size_t)9 * DDIM * IDIM];
__device__ __align__(16) __nv_bfloat16 g_W1l[(size_t)9 * DDIM * IDIM];
__device__ __align__(16) __nv_bfloat16 g_W2h[(size_t)9 * DDIM * IDIM];
__device__ __align__(16) __nv_bfloat16 g_W2l[(size_t)9 * DDIM * IDIM];
__device__ __align__(16) __nv_bfloat16 g_Wdh[(size_t)9 * IDIM * DDIM];
__device__ __align__(16) __nv_bfloat16 g_Wdl[(size_t)9 * IDIM * DDIM];
__device__ __align__(16) __nv_bfloat16 g_Xh[(size_t)NTOK * DDIM];
__device__ __align__(16) __nv_bfloat16 g_Xl[(size_t)NTOK * DDIM];
__device__ __align__(16) __nv_bfloat16 g_Gh[(size_t)MAXROWS * IDIM];
__device__ __align__(16) __nv_bfloat16 g_Gl[(size_t)MAXROWS * IDIM];

__device__ int   g_topk_idx[NTOK * TOPK];
__device__ float g_topk_w[NTOK * TOPK];
__device__ int   g_cnt[NEXP];
__device__ float g_Psum[NEXP];
__device__ int   g_cursor[NEXP];
__device__ int   g_off[NEXP + 1];
__device__ int   g_pair_token[MAXROWS];
__device__ float g_pair_w[MAXROWS];
__device__ int   g_tile_expert[NTILES];

// ---------------- helpers ----------------
__device__ __forceinline__ uint32_t smem_u32(const void* p) {
    uint32_t a;
    asm("{ .reg .u64 t; cvta.to.shared.u64 t, %1; cvt.u32.u64 %0, t; }" : "=r"(a) : "l"(p));
    return a;
}
__device__ __forceinline__ void ldsm_x4(uint32_t* r, uint32_t addr) {
    asm volatile("ldmatrix.sync.aligned.m8n8.x4.shared.b16 {%0,%1,%2,%3}, [%4];"
                 : "=r"(r[0]), "=r"(r[1]), "=r"(r[2]), "=r"(r[3]) : "r"(addr));
}
__device__ __forceinline__ void ldsm_x4_t(uint32_t* r, uint32_t addr) {
    asm volatile("ldmatrix.sync.aligned.m8n8.x4.trans.shared.b16 {%0,%1,%2,%3}, [%4];"
                 : "=r"(r[0]), "=r"(r[1]), "=r"(r[2]), "=r"(r[3]) : "r"(addr));
}
__device__ __forceinline__ void mma16816(float* c, const uint32_t* a, const uint32_t* b) {
    asm volatile("mma.sync.aligned.m16n8k16.row.col.f32.bf16.bf16.f32 "
                 "{%0,%1,%2,%3}, {%4,%5,%6,%7}, {%8,%9}, {%0,%1,%2,%3};"
                 : "+f"(c[0]), "+f"(c[1]), "+f"(c[2]), "+f"(c[3])
                 : "r"(a[0]), "r"(a[1]), "r"(a[2]), "r"(a[3]), "r"(b[0]), "r"(b[1]));
}
__device__ __forceinline__ void split2(float x, float y, uint32_t& hi, uint32_t& lo) {
    __nv_bfloat162 h = __floats2bfloat162_rn(x, y);
    float hx = __bfloat162float(__low2bfloat16(h));
    float hy = __bfloat162float(__high2bfloat16(h));
    __nv_bfloat162 l = __floats2bfloat162_rn(x - hx, y - hy);
    hi = *reinterpret_cast<uint32_t*>(&h);
    lo = *reinterpret_cast<uint32_t*>(&l);
}
__device__ __forceinline__ void cpa16(uint32_t dst, const void* src, uint32_t srcsz) {
    asm volatile("cp.async.cg.shared.global [%0], [%1], 16, %2;"
                 :: "r"(dst), "l"(src), "r"(srcsz) : "memory");
}
#define CP_COMMIT() asm volatile("cp.async.commit_group;" ::: "memory")
#define CP_WAIT(n)  asm volatile("cp.async.wait_group %0;" :: "n"(n) : "memory")

// ---------------- split: fp32 -> bf16 hi + bf16 lo ----------------
__global__ void split_kernel(const float* __restrict__ src,
                             __nv_bfloat16* __restrict__ hi,
                             __nv_bfloat16* __restrict__ lo, int n4) {
    int i = blockIdx.x * blockDim.x + threadIdx.x;
    if (i >= n4) return;
    float4 v = ((const float4*)src)[i];
    uint2 h, l;
    split2(v.x, v.y, h.x, l.x);
    split2(v.z, v.w, h.y, l.y);
    ((uint2*)hi)[i] = h;
    ((uint2*)lo)[i] = l;
}

// ---------------- small kernels ----------------
__global__ void init_kernel() {
    int i = blockIdx.x * blockDim.x + threadIdx.x;
    if (i < NEXP) { g_cnt[i] = 0; g_Psum[i] = 0.f; g_cursor[i] = 0; }
    if (i < MAXROWS) { g_pair_token[i] = -1; g_pair_w[i] = 0.f; }
}

__global__ void routing_kernel(const float* __restrict__ x, const float* __restrict__ Wg) {
    int gwarp = (blockIdx.x * blockDim.x + threadIdx.x) >> 5;
    int lane = threadIdx.x & 31;
    if (gwarp >= NTOK) return;
    const float* xr = x + (size_t)gwarp * DDIM;
    float acc[NEXP];
#pragma unroll
    for (int e = 0; e < NEXP; e++) acc[e] = 0.f;
    for (int j = lane; j < DDIM; j += 32) {
        float xv = xr[j];
        const float* wr = Wg + (size_t)j * NEXP;
#pragma unroll
        for (int e = 0; e < NEXP; e++) acc[e] = fmaf(xv, wr[e], acc[e]);
    }
#pragma unroll
    for (int e = 0; e < NEXP; e++) {
#pragma unroll
        for (int o = 16; o; o >>= 1) acc[e] += __shfl_xor_sync(0xffffffffu, acc[e], o);
    }
    float mx = acc[0];
#pragma unroll
    for (int e = 1; e < NEXP; e++) mx = fmaxf(mx, acc[e]);
    float p[NEXP], s = 0.f;
#pragma unroll
    for (int e = 0; e < NEXP; e++) { p[e] = expf(acc[e] - mx); s += p[e]; }
    float invs = 1.f / s;
#pragma unroll
    for (int e = 0; e < NEXP; e++) p[e] *= invs;
    if (lane < NEXP) atomicAdd(&g_Psum[lane], p[lane]);
    if (lane == 0) {
        int i0 = 0;
#pragma unroll
        for (int e = 1; e < NEXP; e++) if (p[e] > p[i0]) i0 = e;
        int i1 = (i0 == 0) ? 1 : 0;
#pragma unroll
        for (int e = 0; e < NEXP; e++) if (e != i0 && p[e] > p[i1]) i1 = e;
        float w0 = p[i0], w1 = p[i1];
        float inv = 1.f / (w0 + w1 + 1e-9f);
        g_topk_idx[gwarp * 2 + 0] = i0;
        g_topk_idx[gwarp * 2 + 1] = i1;
        g_topk_w[gwarp * 2 + 0] = w0 * inv;
        g_topk_w[gwarp * 2 + 1] = w1 * inv;
        atomicAdd(&g_cnt[i0], 1);
        atomicAdd(&g_cnt[i1], 1);
    }
}

__global__ void offsets_kernel(float* __restrict__ out, int out_size) {
    g_off[0] = 0;
    for (int e = 0; e < NEXP; e++)
        g_off[e + 1] = g_off[e] + ((g_cnt[e] + BM - 1) / BM) * BM;
    for (int t = 0; t < NTILES; t++) {
        int te = 0, r = t * BM;
        for (int e = 0; e < NEXP; e++)
            if (r >= g_off[e] && r < g_off[e + 1]) te = e;
        g_tile_expert[t] = te;
    }
    float aux = 0.f;
    for (int e = 0; e < NEXP; e++) {
        float f = (float)g_cnt[e] / ((float)(NTOK * TOPK) + 1e-9f);
        float P = g_Psum[e] / (float)NTOK;
        aux += f * P;
    }
    out[out_size - 1] = 0.01f * (float)NEXP * aux;
}

__global__ void scatter_kernel() {
    int n = blockIdx.x * blockDim.x + threadIdx.x;
    if (n >= NTOK) return;
#pragma unroll
    for (int k = 0; k < TOPK; k++) {
        int e = g_topk_idx[n * 2 + k];
        int slot = g_off[e] + atomicAdd(&g_cursor[e], 1);
        g_pair_token[slot] = n;
        g_pair_w[slot] = g_topk_w[n * 2 + k];
    }
}

// ---------------- SMEM layout (bf16 tiles, 3-stage pipeline) ----------------
#define STAGES 3
#define A_STRIDE 80                         // 32 bf16 = 64B data, padded
#define A_BYTES  (128 * A_STRIDE)           // 10240 per half
#define UG_BSTRIDE 144                      // 64 bf16 = 128B data
#define UG_BBYTES  (32 * UG_BSTRIDE)        // 4608 per half per matrix
#define UG_AHI 0
#define UG_ALO A_BYTES
#define UG_BGH (2 * A_BYTES)
#define UG_BGL (UG_BGH + UG_BBYTES)
#define UG_BUH (UG_BGL + UG_BBYTES)
#define UG_BUL (UG_BUH + UG_BBYTES)
#define UG_STAGE (UG_BUL + UG_BBYTES)       // 38912
#define UG_SMEM (STAGES * UG_STAGE)         // 116736

#define DN_BSTRIDE 272                      // 128 bf16 = 256B data
#define DN_BBYTES  (32 * DN_BSTRIDE)        // 8704
#define DN_AHI 0
#define DN_ALO A_BYTES
#define DN_BH  (2 * A_BYTES)
#define DN_BL  (DN_BH + DN_BBYTES)
#define DN_STAGE (DN_BL + DN_BBYTES)        // 37888
#define DN_SMEM (STAGES * DN_STAGE)         // 113664

// ---------------- fused up/gate GEMM + SiLU (cp.async pipeline) ----------------
// CTA 128M x 64N; warps 0-3 gate, 4-7 up; warp tile 32x64; BK=32.
template <bool ROUTED>
__global__ void __launch_bounds__(256)
upgate_mma() {
    extern __shared__ char smem[];
    uint32_t sb = smem_u32(smem);
    int tid = threadIdx.x;
    int wid = tid >> 5, lane = tid & 31;
    int m0 = blockIdx.y * BM, n0 = blockIdx.x * 64;
    if (ROUTED && m0 >= g_off[NEXP]) return;
    int e = ROUTED ? g_tile_expert[blockIdx.y] : NEXP;

    const __nv_bfloat16* w1h = g_W1h + (size_t)e * DDIM * IDIM;
    const __nv_bfloat16* w1l = g_W1l + (size_t)e * DDIM * IDIM;
    const __nv_bfloat16* w2h = g_W2h + (size_t)e * DDIM * IDIM;
    const __nv_bfloat16* w2l = g_W2l + (size_t)e * DDIM * IDIM;

    // A loader: 2 chunk-rows per thread (rows r0 and r0+64), 16B each (8 bf16)
    int r0 = tid >> 2, kq = (tid & 3) * 8;
    int r1 = r0 + 64;
    int t0 = ROUTED ? g_pair_token[m0 + r0] : (m0 + r0);
    int t1 = ROUTED ? g_pair_token[m0 + r1] : (m0 + r1);
    uint32_t sz0 = (t0 >= 0) ? 16u : 0u;
    uint32_t sz1 = (t1 >= 0) ? 16u : 0u;
    const __nv_bfloat16* a0h = g_Xh + (size_t)(t0 >= 0 ? t0 : 0) * DDIM + kq;
    const __nv_bfloat16* a0l = g_Xl + (size_t)(t0 >= 0 ? t0 : 0) * DDIM + kq;
    const __nv_bfloat16* a1h = g_Xh + (size_t)(t1 >= 0 ? t1 : 0) * DDIM + kq;
    const __nv_bfloat16* a1l = g_Xl + (size_t)(t1 >= 0 ? t1 : 0) * DDIM + kq;
    uint32_t dA0 = UG_AHI + (uint32_t)(r0 * A_STRIDE + kq * 2);
    uint32_t dA1 = UG_AHI + (uint32_t)(r1 * A_STRIDE + kq * 2);
    // B loader: row br (0..31), 16B chunk at col bn
    int br = tid >> 3, bn = (tid & 7) * 8;
    uint32_t dB = (uint32_t)(br * UG_BSTRIDE + bn * 2);
    size_t bsrc0 = (size_t)br * IDIM + n0 + bn;

    const int NST = DDIM / 32;  // 32

#define UG_ISSUE(s_) do { \
        uint32_t st = sb + (uint32_t)(((s_) % STAGES) * UG_STAGE); \
        int k0 = (s_) * 32; \
        cpa16(st + dA0, a0h + k0, sz0); \
        cpa16(st + dA0 + (UG_ALO - UG_AHI), a0l + k0, sz0); \
        cpa16(st + dA1, a1h + k0, sz1); \
        cpa16(st + dA1 + (UG_ALO - UG_AHI), a1l + k0, sz1); \
        size_t bo = bsrc0 + (size_t)k0 * IDIM; \
        cpa16(st + UG_BGH + dB, w1h + bo, 16u); \
        cpa16(st + UG_BGL + dB, w1l + bo, 16u); \
        cpa16(st + UG_BUH + dB, w2h + bo, 16u); \
        cpa16(st + UG_BUL + dB, w2l + bo, 16u); \
    } while (0)

    UG_ISSUE(0); CP_COMMIT();
    UG_ISSUE(1); CP_COMMIT();

    // fragment lane addressing
    int arow_l = (lane & 7) + ((lane >> 3) & 1) * 8;
    int akc_l = (lane >> 4) * 8;
    int mw = (wid & 3) * 32;
    bool isGate = (wid < 4);
    uint32_t bBaseH = isGate ? UG_BGH : UG_BUH;
    uint32_t bBaseL = isGate ? UG_BGL : UG_BUL;

    float acc[2][8][4];
#pragma unroll
    for (int i = 0; i < 2; i++)
#pragma unroll
        for (int j = 0; j < 8; j++)
#pragma unroll
            for (int q = 0; q < 4; q++) acc[i][j][q] = 0.f;

    for (int s = 0; s < NST; s++) {
        CP_WAIT(1);
        __syncthreads();
        if (s + 2 < NST) UG_ISSUE(s + 2);
        CP_COMMIT();
        uint32_t stg = sb + (uint32_t)((s % STAGES) * UG_STAGE);
#pragma unroll
        for (int ks = 0; ks < 32; ks += 16) {
            uint32_t aH[2][4], aL[2][4];
#pragma unroll
            for (int mt = 0; mt < 2; mt++) {
                uint32_t ao = (mw + mt * 16 + arow_l) * A_STRIDE + (ks + akc_l) * 2;
                ldsm_x4(aH[mt], stg + UG_AHI + ao);
                ldsm_x4(aL[mt], stg + UG_ALO + ao);
            }
#pragma unroll
            for (int g = 0; g < 4; g++) {
                uint32_t bo = (ks + arow_l) * UG_BSTRIDE + (g * 16 + akc_l) * 2;
                uint32_t bH[4], bL[4];
                ldsm_x4_t(bH, stg + bBaseH + bo);
                ldsm_x4_t(bL, stg + bBaseL + bo);
#pragma unroll
                for (int mt = 0; mt < 2; mt++)
#pragma unroll
                    for (int sub = 0; sub < 2; sub++) {
                        float* c = acc[mt][g * 2 + sub];
                        mma16816(c, aH[mt], bH + sub * 2);
                        mma16816(c, aH[mt], bL + sub * 2);
                        mma16816(c, aL[mt], bH + sub * 2);
                    }
            }
        }
    }
    CP_WAIT(0);
    __syncthreads();

    // epilogue: exchange up through smem, apply SiLU, write G as bf16 hi/lo
    float* exch = (float*)smem;
    int fr = lane >> 2, fc = (lane & 3) * 2;
    if (!isGate) {
#pragma unroll
        for (int mt = 0; mt < 2; mt++)
#pragma unroll
            for (int j = 0; j < 8; j++) {
                float* c = acc[mt][j];
                int r = mw + mt * 16 + fr, cl = j * 8 + fc;
                *(float2*)&exch[r * 64 + cl] = make_float2(c[0], c[1]);
                *(float2*)&exch[(r + 8) * 64 + cl] = make_float2(c[2], c[3]);
            }
    }
    __syncthreads();
    if (isGate) {
#pragma unroll
        for (int mt = 0; mt < 2; mt++)
#pragma unroll
            for (int j = 0; j < 8; j++) {
                float* c = acc[mt][j];
                int r = mw + mt * 16 + fr, cl = j * 8 + fc;
                float2 u0 = *(float2*)&exch[r * 64 + cl];
                float2 u1 = *(float2*)&exch[(r + 8) * 64 + cl];
                float2 g0, g1;
                g0.x = c[0] / (1.f + __expf(-c[0])) * u0.x;
                g0.y = c[1] / (1.f + __expf(-c[1])) * u0.y;
                g1.x = c[2] / (1.f + __expf(-c[2])) * u1.x;
                g1.y = c[3] / (1.f + __expf(-c[3])) * u1.y;
                *(float2*)&exch[r * 64 + cl] = g0;
                *(float2*)&exch[(r + 8) * 64 + cl] = g1;
            }
    }
    __syncthreads();
    {
        int r = tid >> 1, cb = (tid & 1) * 32;
        const float4* src = (const float4*)&exch[r * 64 + cb];
        __nv_bfloat16* dh = g_Gh + (size_t)(m0 + r) * IDIM + n0 + cb;
        __nv_bfloat16* dl = g_Gl + (size_t)(m0 + r) * IDIM + n0 + cb;
#pragma unroll
        for (int j = 0; j < 8; j++) {
            float4 v = src[j];
            uint2 h, l;
            split2(v.x, v.y, h.x, l.x);
            split2(v.z, v.w, h.y, l.y);
            ((uint2*)dh)[j] = h;
            ((uint2*)dl)[j] = l;
        }
    }
#undef UG_ISSUE
}

// ---------------- down GEMM (cp.async pipeline) ----------------
// CTA 128M x 128N; warps 4x2; warp tile 32x64; BK=32; K=IDIM.
template <bool ROUTED>
__global__ void __launch_bounds__(256)
down_mma(float* __restrict__ out) {
    extern __shared__ char smem[];
    uint32_t sb = smem_u32(smem);
    int tid = threadIdx.x;
    int wid = tid >> 5, lane = tid & 31;
    int m0 = blockIdx.y * BM, n0 = blockIdx.x * 128;
    if (ROUTED && m0 >= g_off[NEXP]) return;
    int e = ROUTED ? g_tile_expert[blockIdx.y] : NEXP;

    const __nv_bfloat16* wh = g_Wdh + (size_t)e * IDIM * DDIM;
    const __nv_bfloat16* wl = g_Wdl + (size_t)e * IDIM * DDIM;

    // A loader: rows r0, r0+64 from G (expert-sorted; no gather)
    int r0 = tid >> 2, kq = (tid & 3) * 8;
    int r1 = r0 + 64;
    const __nv_bfloat16* a0h = g_Gh + (size_t)(m0 + r0) * IDIM + kq;
    const __nv_bfloat16* a0l = g_Gl + (size_t)(m0 + r0) * IDIM + kq;
    const __nv_bfloat16* a1h = g_Gh + (size_t)(m0 + r1) * IDIM + kq;
    const __nv_bfloat16* a1l = g_Gl + (size_t)(m0 + r1) * IDIM + kq;
    uint32_t dA0 = DN_AHI + (uint32_t)(r0 * A_STRIDE + kq * 2);
    uint32_t dA1 = DN_AHI + (uint32_t)(r1 * A_STRIDE + kq * 2);
    // B loader: rows br0=tid>>4 (0..15) and +16; 16B chunk at col bnc
    int br0 = tid >> 4, bnc = (tid & 15) * 8;
    int br1 = br0 + 16;
    uint32_t dB0 = (uint32_t)(br0 * DN_BSTRIDE + bnc * 2);
    uint32_t dB1 = (uint32_t)(br1 * DN_BSTRIDE + bnc * 2);
    size_t bs0 = (size_t)br0 * DDIM + n0 + bnc;
    size_t bs1 = (size_t)br1 * DDIM + n0 + bnc;

    const int NST = IDIM / 32;  // 64

#define DN_ISSUE(s_) do { \
        uint32_t st = sb + (uint32_t)(((s_) % STAGES) * DN_STAGE); \
        int k0 = (s_) * 32; \
        cpa16(st + dA0, a0h + k0, 16u); \
        cpa16(st + dA0 + (DN_ALO - DN_AHI), a0l + k0, 16u); \
        cpa16(st + dA1, a1h + k0, 16u); \
        cpa16(st + dA1 + (DN_ALO - DN_AHI), a1l + k0, 16u); \
        size_t o0 = bs0 + (size_t)k0 * DDIM, o1 = bs1 + (size_t)k0 * DDIM; \
        cpa16(st + DN_BH + dB0, wh + o0, 16u); \
        cpa16(st + DN_BL + dB0, wl + o0, 16u); \
        cpa16(st + DN_BH + dB1, wh + o1, 16u); \
        cpa16(st + DN_BL + dB1, wl + o1, 16u); \
    } while (0)

    DN_ISSUE(0); CP_COMMIT();
    DN_ISSUE(1); CP_COMMIT();

    int arow_l = (lane & 7) + ((lane >> 3) & 1) * 8;
    int akc_l = (lane >> 4) * 8;
    int mw = (wid >> 1) * 32;
    int nwo = (wid & 1) * 64;

    float acc[2][8][4];
#pragma unroll
    for (int i = 0; i < 2; i++)
#pragma unroll
        for (int j = 0; j < 8; j++)
#pragma unroll
            for (int q = 0; q < 4; q++) acc[i][j][q] = 0.f;

    for (int s = 0; s < NST; s++) {
        CP_WAIT(1);
        __syncthreads();
        if (s + 2 < NST) DN_ISSUE(s + 2);
        CP_COMMIT();
        uint32_t stg = sb + (uint32_t)((s % STAGES) * DN_STAGE);
#pragma unroll
        for (int ks = 0; ks < 32; ks += 16) {
            uint32_t aH[2][4], aL[2][4];
#pragma unroll
            for (int mt = 0; mt < 2; mt++) {
                uint32_t ao = (mw + mt * 16 + arow_l) * A_STRIDE + (ks + akc_l) * 2;
                ldsm_x4(aH[mt], stg + DN_AHI + ao);
                ldsm_x4(aL[mt], stg + DN_ALO + ao);
            }
#pragma unroll
            for (int g = 0; g < 4; g++) {
                uint32_t bo = (ks + arow_l) * DN_BSTRIDE + (nwo + g * 16 + akc_l) * 2;
                uint32_t bH[4], bL[4];
                ldsm_x4_t(bH, stg + DN_BH + bo);
                ldsm_x4_t(bL, stg + DN_BL + bo);
#pragma unroll
                for (int mt = 0; mt < 2; mt++)
#pragma unroll
                    for (int sub = 0; sub < 2; sub++) {
                        float* c = acc[mt][g * 2 + sub];
                        mma16816(c, aH[mt], bH + sub * 2);
                        mma16816(c, aH[mt], bL + sub * 2);
                        mma16816(c, aL[mt], bH + sub * 2);
                    }
            }
        }
    }
    CP_WAIT(0);
    __syncthreads();

    // stage C (128x128 fp32) in smem for coalesced output
    float* Cs = (float*)smem;
    int fr = lane >> 2, fc = (lane & 3) * 2;
#pragma unroll
    for (int mt = 0; mt < 2; mt++)
#pragma unroll
        for (int j = 0; j < 8; j++) {
            float* c = acc[mt][j];
            int r = mw + mt * 16 + fr, cl = nwo + j * 8 + fc;
            *(float2*)&Cs[r * 128 + cl] = make_float2(c[0], c[1]);
            *(float2*)&Cs[(r + 8) * 128 + cl] = make_float2(c[2], c[3]);
        }
    __syncthreads();

    int r = tid >> 1, cb = (tid & 1) * 64;
    if (!ROUTED) {
        float* dst = out + (size_t)(m0 + r) * DDIM + n0 + cb;
#pragma unroll
        for (int j = 0; j < 16; j++)
            ((float4*)dst)[j] = ((const float4*)&Cs[r * 128 + cb])[j];
    } else {
        int tokr = g_pair_token[m0 + r];
        if (tokr >= 0) {
            float wgt = g_pair_w[m0 + r];
            float* dst = out + (size_t)tokr * DDIM + n0 + cb;
            const float* src = &Cs[r * 128 + cb];
#pragma unroll
            for (int j = 0; j < 64; j++)
                atomicAdd(dst + j, wgt * src[j]);
        }
    }
#undef DN_ISSUE
}

// ---------------- launch ----------------
static inline void launch_split(const float* src, __nv_bfloat16* hi, __nv_bfloat16* lo, size_t n) {
    int n4 = (int)(n / 4);
    split_kernel<<<(n4 + 255) / 256, 256>>>(src, hi, lo, n4);
}

extern "C" void kernel_launch(void* const* d_in, const int* in_sizes, int n_in,
                              void* d_out, int out_size) {
    const float* x       = (const float*)d_in[0];
    const float* Wg      = (const float*)d_in[1];
    const float* W_gate  = (const float*)d_in[2];
    const float* W_up    = (const float*)d_in[3];
    const float* W_down  = (const float*)d_in[4];
    const float* Ws_gate = (const float*)d_in[5];
    const float* Ws_up   = (const float*)d_in[6];
    const float* Ws_down = (const float*)d_in[7];
    float* out = (float*)d_out;

    cudaFuncSetAttribute(upgate_mma<false>, cudaFuncAttributeMaxDynamicSharedMemorySize, UG_SMEM);
    cudaFuncSetAttribute(upgate_mma<true>,  cudaFuncAttributeMaxDynamicSharedMemorySize, UG_SMEM);
    cudaFuncSetAttribute(down_mma<false>,   cudaFuncAttributeMaxDynamicSharedMemorySize, DN_SMEM);
    cudaFuncSetAttribute(down_mma<true>,    cudaFuncAttributeMaxDynamicSharedMemorySize, DN_SMEM);

    // resolve device-global addresses (host-side)
    __nv_bfloat16 *w1h, *w1l, *w2h, *w2l, *wdh, *wdl, *xh, *xl;
    cudaGetSymbolAddress((void**)&w1h, g_W1h);
    cudaGetSymbolAddress((void**)&w1l, g_W1l);
    cudaGetSymbolAddress((void**)&w2h, g_W2h);
    cudaGetSymbolAddress((void**)&w2l, g_W2l);
    cudaGetSymbolAddress((void**)&wdh, g_Wdh);
    cudaGetSymbolAddress((void**)&wdl, g_Wdl);
    cudaGetSymbolAddress((void**)&xh, g_Xh);
    cudaGetSymbolAddress((void**)&xl, g_Xl);

    const size_t WSZ = (size_t)DDIM * IDIM;       // per-expert weight elems
    const size_t SHO = (size_t)NEXP * WSZ;        // shared-expert offset (e=8)

    init_kernel<<<(MAXROWS + 255) / 256, 256>>>();
    routing_kernel<<<(NTOK * 32 + 255) / 256, 256>>>(x, Wg);
    offsets_kernel<<<1, 1>>>(out, out_size);
    scatter_kernel<<<(NTOK + 255) / 256, 256>>>();

    // pre-split everything to bf16 hi/lo
    launch_split(x,       xh,        xl,        (size_t)NTOK * DDIM);
    launch_split(W_gate,  w1h,       w1l,       SHO);
    launch_split(Ws_gate, w1h + SHO, w1l + SHO, WSZ);
    launch_split(W_up,    w2h,       w2l,       SHO);
    launch_split(Ws_up,   w2h + SHO, w2l + SHO, WSZ);
    launch_split(W_down,  wdh,       wdl,       SHO);
    launch_split(Ws_down, wdh + SHO, wdl + SHO, WSZ);

    // shared expert (e=8)
    upgate_mma<false><<<dim3(IDIM / 64, NTOK / BM), 256, UG_SMEM>>>();
    down_mma<false><<<dim3(DDIM / 128, NTOK / BM), 256, DN_SMEM>>>(out);

    // routed experts (expert-sorted, 128-padded segments)
    upgate_mma<true><<<dim3(IDIM / 64, NTILES), 256, UG_SMEM>>>();
    down_mma<true><<<dim3(DDIM / 128, NTILES), 256, DN_SMEM>>>(out);
}

// round 5
// speedup vs baseline: 5.0436x; 2.2484x over previous
#include <cuda_runtime.h>
#include <cuda_fp16.h>
#include <math.h>
#include <stdint.h>

// Problem constants (B=2, S=2048 -> N=4096 tokens)
#define NTOK 4096
#define DDIM 1024
#define IDIM 2048
#define NEXP 8
#define TOPK 2
#define BM   128
#define MAXROWS 9216
#define NTILES  72

// ---------------- scratch (device globals) ----------------
// single fp16 copies. expert index 8 = shared expert.
__device__ __align__(16) __half g_W1[(size_t)9 * DDIM * IDIM];
__device__ __align__(16) __half g_W2[(size_t)9 * DDIM * IDIM];
__device__ __align__(16) __half g_Wd[(size_t)9 * IDIM * DDIM];
__device__ __align__(16) __half g_X[(size_t)NTOK * DDIM];
__device__ __align__(16) __half g_Gf[(size_t)MAXROWS * IDIM];

__device__ int   g_topk_idx[NTOK * TOPK];
__device__ float g_topk_w[NTOK * TOPK];
__device__ int   g_cnt[NEXP];
__device__ float g_Psum[NEXP];
__device__ int   g_cursor[NEXP];
__device__ int   g_off[NEXP + 1];
__device__ int   g_pair_token[MAXROWS];
__device__ float g_pair_w[MAXROWS];
__device__ int   g_tile_expert[NTILES];

// ---------------- helpers ----------------
__device__ __forceinline__ uint32_t smem_u32(const void* p) {
    uint32_t a;
    asm("{ .reg .u64 t; cvta.to.shared.u64 t, %1; cvt.u32.u64 %0, t; }" : "=r"(a) : "l"(p));
    return a;
}
__device__ __forceinline__ void ldsm_x4(uint32_t* r, uint32_t addr) {
    asm volatile("ldmatrix.sync.aligned.m8n8.x4.shared.b16 {%0,%1,%2,%3}, [%4];"
                 : "=r"(r[0]), "=r"(r[1]), "=r"(r[2]), "=r"(r[3]) : "r"(addr));
}
__device__ __forceinline__ void ldsm_x4_t(uint32_t* r, uint32_t addr) {
    asm volatile("ldmatrix.sync.aligned.m8n8.x4.trans.shared.b16 {%0,%1,%2,%3}, [%4];"
                 : "=r"(r[0]), "=r"(r[1]), "=r"(r[2]), "=r"(r[3]) : "r"(addr));
}
__device__ __forceinline__ void mma16816(float* c, const uint32_t* a, const uint32_t* b) {
    asm volatile("mma.sync.aligned.m16n8k16.row.col.f32.f16.f16.f32 "
                 "{%0,%1,%2,%3}, {%4,%5,%6,%7}, {%8,%9}, {%0,%1,%2,%3};"
                 : "+f"(c[0]), "+f"(c[1]), "+f"(c[2]), "+f"(c[3])
                 : "r"(a[0]), "r"(a[1]), "r"(a[2]), "r"(a[3]), "r"(b[0]), "r"(b[1]));
}
__device__ __forceinline__ void cpa16(uint32_t dst, const void* src, uint32_t srcsz) {
    asm volatile("cp.async.cg.shared.global [%0], [%1], 16, %2;"
                 :: "r"(dst), "l"(src), "r"(srcsz) : "memory");
}
#define CP_COMMIT() asm volatile("cp.async.commit_group;" ::: "memory")
#define CP_WAIT(n)  asm volatile("cp.async.wait_group %0;" :: "n"(n) : "memory")

// ---------------- convert: fp32 -> fp16 ----------------
__global__ void cvt_kernel(const float* __restrict__ src, __half* __restrict__ dst, int n4) {
    int i = blockIdx.x * blockDim.x + threadIdx.x;
    if (i >= n4) return;
    float4 v = ((const float4*)src)[i];
    __half2 h0 = __floats2half2_rn(v.x, v.y);
    __half2 h1 = __floats2half2_rn(v.z, v.w);
    uint2 o;
    o.x = *reinterpret_cast<uint32_t*>(&h0);
    o.y = *reinterpret_cast<uint32_t*>(&h1);
    ((uint2*)dst)[i] = o;
}

// ---------------- small kernels ----------------
__global__ void init_kernel() {
    int i = blockIdx.x * blockDim.x + threadIdx.x;
    if (i < NEXP) { g_cnt[i] = 0; g_Psum[i] = 0.f; g_cursor[i] = 0; }
    if (i < MAXROWS) { g_pair_token[i] = -1; g_pair_w[i] = 0.f; }
}

__global__ void routing_kernel(const float* __restrict__ x, const float* __restrict__ Wg) {
    int gwarp = (blockIdx.x * blockDim.x + threadIdx.x) >> 5;
    int lane = threadIdx.x & 31;
    if (gwarp >= NTOK) return;
    const float* xr = x + (size_t)gwarp * DDIM;
    float acc[NEXP];
#pragma unroll
    for (int e = 0; e < NEXP; e++) acc[e] = 0.f;
    for (int j = lane; j < DDIM; j += 32) {
        float xv = xr[j];
        const float* wr = Wg + (size_t)j * NEXP;
#pragma unroll
        for (int e = 0; e < NEXP; e++) acc[e] = fmaf(xv, wr[e], acc[e]);
    }
#pragma unroll
    for (int e = 0; e < NEXP; e++) {
#pragma unroll
        for (int o = 16; o; o >>= 1) acc[e] += __shfl_xor_sync(0xffffffffu, acc[e], o);
    }
    float mx = acc[0];
#pragma unroll
    for (int e = 1; e < NEXP; e++) mx = fmaxf(mx, acc[e]);
    float p[NEXP], s = 0.f;
#pragma unroll
    for (int e = 0; e < NEXP; e++) { p[e] = expf(acc[e] - mx); s += p[e]; }
    float invs = 1.f / s;
#pragma unroll
    for (int e = 0; e < NEXP; e++) p[e] *= invs;
    if (lane < NEXP) atomicAdd(&g_Psum[lane], p[lane]);
    if (lane == 0) {
        int i0 = 0;
#pragma unroll
        for (int e = 1; e < NEXP; e++) if (p[e] > p[i0]) i0 = e;
        int i1 = (i0 == 0) ? 1 : 0;
#pragma unroll
        for (int e = 0; e < NEXP; e++) if (e != i0 && p[e] > p[i1]) i1 = e;
        float w0 = p[i0], w1 = p[i1];
        float inv = 1.f / (w0 + w1 + 1e-9f);
        g_topk_idx[gwarp * 2 + 0] = i0;
        g_topk_idx[gwarp * 2 + 1] = i1;
        g_topk_w[gwarp * 2 + 0] = w0 * inv;
        g_topk_w[gwarp * 2 + 1] = w1 * inv;
        atomicAdd(&g_cnt[i0], 1);
        atomicAdd(&g_cnt[i1], 1);
    }
}

__global__ void offsets_kernel(float* __restrict__ out, int out_size) {
    g_off[0] = 0;
    for (int e = 0; e < NEXP; e++)
        g_off[e + 1] = g_off[e] + ((g_cnt[e] + BM - 1) / BM) * BM;
    for (int t = 0; t < NTILES; t++) {
        int te = 0, r = t * BM;
        for (int e = 0; e < NEXP; e++)
            if (r >= g_off[e] && r < g_off[e + 1]) te = e;
        g_tile_expert[t] = te;
    }
    float aux = 0.f;
    for (int e = 0; e < NEXP; e++) {
        float f = (float)g_cnt[e] / ((float)(NTOK * TOPK) + 1e-9f);
        float P = g_Psum[e] / (float)NTOK;
        aux += f * P;
    }
    out[out_size - 1] = 0.01f * (float)NEXP * aux;
}

__global__ void scatter_kernel() {
    int n = blockIdx.x * blockDim.x + threadIdx.x;
    if (n >= NTOK) return;
#pragma unroll
    for (int k = 0; k < TOPK; k++) {
        int e = g_topk_idx[n * 2 + k];
        int slot = g_off[e] + atomicAdd(&g_cursor[e], 1);
        g_pair_token[slot] = n;
        g_pair_w[slot] = g_topk_w[n * 2 + k];
    }
}

// ---------------- SMEM layout (fp16 tiles, 4-stage pipeline) ----------------
#define STAGES 4
#define A_STRIDE 80                         // 32 fp16 = 64B data, pad to 80 (conflict-free ldsm)
#define A_BYTES  (128 * A_STRIDE)           // 10240
#define UG_BSTRIDE 144                      // 64 fp16 = 128B data
#define UG_BBYTES  (32 * UG_BSTRIDE)        // 4608 per matrix
#define UG_A  0
#define UG_BG A_BYTES
#define UG_BU (UG_BG + UG_BBYTES)
#define UG_STAGE (UG_BU + UG_BBYTES)        // 19456
#define UG_SMEM (STAGES * UG_STAGE)         // 77824

#define DN_BSTRIDE 272                      // 128 fp16 = 256B data
#define DN_BBYTES  (32 * DN_BSTRIDE)        // 8704
#define DN_A  0
#define DN_B  A_BYTES
#define DN_STAGE (DN_B + DN_BBYTES)         // 18944
#define DN_SMEM (STAGES * DN_STAGE)         // 75776

// ---------------- fused up/gate GEMM + SiLU ----------------
// CTA 128M x 64N; warps 0-3 gate, 4-7 up; warp tile 32x64; BK=32.
template <bool ROUTED>
__global__ void __launch_bounds__(256)
upgate_mma() {
    extern __shared__ char smem[];
    uint32_t sb = smem_u32(smem);
    int tid = threadIdx.x;
    int wid = tid >> 5, lane = tid & 31;
    int m0 = blockIdx.y * BM, n0 = blockIdx.x * 64;
    if (ROUTED && m0 >= g_off[NEXP]) return;
    int e = ROUTED ? g_tile_expert[blockIdx.y] : NEXP;

    const __half* w1 = g_W1 + (size_t)e * DDIM * IDIM;
    const __half* w2 = g_W2 + (size_t)e * DDIM * IDIM;

    // A loader: rows r0 and r0+64, one 16B chunk (8 fp16) each
    int r0 = tid >> 2, kq = (tid & 3) * 8;
    int r1 = r0 + 64;
    int t0 = ROUTED ? g_pair_token[m0 + r0] : (m0 + r0);
    int t1 = ROUTED ? g_pair_token[m0 + r1] : (m0 + r1);
    uint32_t sz0 = (t0 >= 0) ? 16u : 0u;
    uint32_t sz1 = (t1 >= 0) ? 16u : 0u;
    const __half* a0 = g_X + (size_t)(t0 >= 0 ? t0 : 0) * DDIM + kq;
    const __half* a1 = g_X + (size_t)(t1 >= 0 ? t1 : 0) * DDIM + kq;
    uint32_t dA0 = UG_A + (uint32_t)(r0 * A_STRIDE + kq * 2);
    uint32_t dA1 = UG_A + (uint32_t)(r1 * A_STRIDE + kq * 2);
    // B loader: row br (0..31), one 16B chunk at col bn per matrix
    int br = tid >> 3, bn = (tid & 7) * 8;
    uint32_t dB = (uint32_t)(br * UG_BSTRIDE + bn * 2);
    size_t bsrc0 = (size_t)br * IDIM + n0 + bn;

    const int NST = DDIM / 32;  // 32

#define UG_ISSUE(s_) do { \
        uint32_t st = sb + (uint32_t)(((s_) % STAGES) * UG_STAGE); \
        int k0 = (s_) * 32; \
        cpa16(st + dA0, a0 + k0, sz0); \
        cpa16(st + dA1, a1 + k0, sz1); \
        size_t bo = bsrc0 + (size_t)k0 * IDIM; \
        cpa16(st + UG_BG + dB, w1 + bo, 16u); \
        cpa16(st + UG_BU + dB, w2 + bo, 16u); \
    } while (0)

    UG_ISSUE(0); CP_COMMIT();
    UG_ISSUE(1); CP_COMMIT();
    UG_ISSUE(2); CP_COMMIT();

    int arow_l = (lane & 7) + ((lane >> 3) & 1) * 8;
    int akc_l = (lane >> 4) * 8;
    int mw = (wid & 3) * 32;
    bool isGate = (wid < 4);
    uint32_t bBase = isGate ? UG_BG : UG_BU;

    float acc[2][8][4];
#pragma unroll
    for (int i = 0; i < 2; i++)
#pragma unroll
        for (int j = 0; j < 8; j++)
#pragma unroll
            for (int q = 0; q < 4; q++) acc[i][j][q] = 0.f;

    for (int s = 0; s < NST; s++) {
        CP_WAIT(2);
        __syncthreads();
        if (s + 3 < NST) UG_ISSUE(s + 3);
        CP_COMMIT();
        uint32_t stg = sb + (uint32_t)((s % STAGES) * UG_STAGE);
#pragma unroll
        for (int ks = 0; ks < 32; ks += 16) {
            uint32_t aF[2][4];
#pragma unroll
            for (int mt = 0; mt < 2; mt++) {
                uint32_t ao = (mw + mt * 16 + arow_l) * A_STRIDE + (ks + akc_l) * 2;
                ldsm_x4(aF[mt], stg + UG_A + ao);
            }
#pragma unroll
            for (int g = 0; g < 4; g++) {
                uint32_t bo = (ks + arow_l) * UG_BSTRIDE + (g * 16 + akc_l) * 2;
                uint32_t bF[4];
                ldsm_x4_t(bF, stg + bBase + bo);
#pragma unroll
                for (int mt = 0; mt < 2; mt++)
#pragma unroll
                    for (int sub = 0; sub < 2; sub++)
                        mma16816(acc[mt][g * 2 + sub], aF[mt], bF + sub * 2);
            }
        }
    }
    CP_WAIT(0);
    __syncthreads();

    // epilogue: exchange up through smem, apply SiLU, write G fp16
    float* exch = (float*)smem;
    int fr = lane >> 2, fc = (lane & 3) * 2;
    if (!isGate) {
#pragma unroll
        for (int mt = 0; mt < 2; mt++)
#pragma unroll
            for (int j = 0; j < 8; j++) {
                float* c = acc[mt][j];
                int r = mw + mt * 16 + fr, cl = j * 8 + fc;
                *(float2*)&exch[r * 64 + cl] = make_float2(c[0], c[1]);
                *(float2*)&exch[(r + 8) * 64 + cl] = make_float2(c[2], c[3]);
            }
    }
    __syncthreads();
    if (isGate) {
#pragma unroll
        for (int mt = 0; mt < 2; mt++)
#pragma unroll
            for (int j = 0; j < 8; j++) {
                float* c = acc[mt][j];
                int r = mw + mt * 16 + fr, cl = j * 8 + fc;
                float2 u0 = *(float2*)&exch[r * 64 + cl];
                float2 u1 = *(float2*)&exch[(r + 8) * 64 + cl];
                float2 g0, g1;
                g0.x = c[0] / (1.f + __expf(-c[0])) * u0.x;
                g0.y = c[1] / (1.f + __expf(-c[1])) * u0.y;
                g1.x = c[2] / (1.f + __expf(-c[2])) * u1.x;
                g1.y = c[3] / (1.f + __expf(-c[3])) * u1.y;
                *(float2*)&exch[r * 64 + cl] = g0;
                *(float2*)&exch[(r + 8) * 64 + cl] = g1;
            }
    }
    __syncthreads();
    {
        int r = tid >> 1, cb = (tid & 1) * 32;
        const float4* src = (const float4*)&exch[r * 64 + cb];
        __half* dst = g_Gf + (size_t)(m0 + r) * IDIM + n0 + cb;
#pragma unroll
        for (int j = 0; j < 8; j++) {
            float4 v = src[j];
            __half2 h0 = __floats2half2_rn(v.x, v.y);
            __half2 h1 = __floats2half2_rn(v.z, v.w);
            uint2 o;
            o.x = *reinterpret_cast<uint32_t*>(&h0);
            o.y = *reinterpret_cast<uint32_t*>(&h1);
            ((uint2*)dst)[j] = o;
        }
    }
#undef UG_ISSUE
}

// ---------------- down GEMM ----------------
// CTA 128M x 128N; warps 4x2; warp tile 32x64; BK=32; K=IDIM.
template <bool ROUTED>
__global__ void __launch_bounds__(256)
down_mma(float* __restrict__ out) {
    extern __shared__ char smem[];
    uint32_t sb = smem_u32(smem);
    int tid = threadIdx.x;
    int wid = tid >> 5, lane = tid & 31;
    int m0 = blockIdx.y * BM, n0 = blockIdx.x * 128;
    if (ROUTED && m0 >= g_off[NEXP]) return;
    int e = ROUTED ? g_tile_expert[blockIdx.y] : NEXP;

    const __half* w = g_Wd + (size_t)e * IDIM * DDIM;

    int r0 = tid >> 2, kq = (tid & 3) * 8;
    int r1 = r0 + 64;
    const __half* a0 = g_Gf + (size_t)(m0 + r0) * IDIM + kq;
    const __half* a1 = g_Gf + (size_t)(m0 + r1) * IDIM + kq;
    uint32_t dA0 = DN_A + (uint32_t)(r0 * A_STRIDE + kq * 2);
    uint32_t dA1 = DN_A + (uint32_t)(r1 * A_STRIDE + kq * 2);
    // B loader: rows br0 (0..15) and br0+16, 16B chunk at col bnc
    int br0 = tid >> 4, bnc = (tid & 15) * 8;
    int br1 = br0 + 16;
    uint32_t dB0 = (uint32_t)(br0 * DN_BSTRIDE + bnc * 2);
    uint32_t dB1 = (uint32_t)(br1 * DN_BSTRIDE + bnc * 2);
    size_t bs0 = (size_t)br0 * DDIM + n0 + bnc;
    size_t bs1 = (size_t)br1 * DDIM + n0 + bnc;

    const int NST = IDIM / 32;  // 64

#define DN_ISSUE(s_) do { \
        uint32_t st = sb + (uint32_t)(((s_) % STAGES) * DN_STAGE); \
        int k0 = (s_) * 32; \
        cpa16(st + dA0, a0 + k0, 16u); \
        cpa16(st + dA1, a1 + k0, 16u); \
        size_t o0 = bs0 + (size_t)k0 * DDIM, o1 = bs1 + (size_t)k0 * DDIM; \
        cpa16(st + DN_B + dB0, w + o0, 16u); \
        cpa16(st + DN_B + dB1, w + o1, 16u); \
    } while (0)

    DN_ISSUE(0); CP_COMMIT();
    DN_ISSUE(1); CP_COMMIT();
    DN_ISSUE(2); CP_COMMIT();

    int arow_l = (lane & 7) + ((lane >> 3) & 1) * 8;
    int akc_l = (lane >> 4) * 8;
    int mw = (wid >> 1) * 32;
    int nwo = (wid & 1) * 64;

    float acc[2][8][4];
#pragma unroll
    for (int i = 0; i < 2; i++)
#pragma unroll
        for (int j = 0; j < 8; j++)
#pragma unroll
            for (int q = 0; q < 4; q++) acc[i][j][q] = 0.f;

    for (int s = 0; s < NST; s++) {
        CP_WAIT(2);
        __syncthreads();
        if (s + 3 < NST) DN_ISSUE(s + 3);
        CP_COMMIT();
        uint32_t stg = sb + (uint32_t)((s % STAGES) * DN_STAGE);
#pragma unroll
        for (int ks = 0; ks < 32; ks += 16) {
            uint32_t aF[2][4];
#pragma unroll
            for (int mt = 0; mt < 2; mt++) {
                uint32_t ao = (mw + mt * 16 + arow_l) * A_STRIDE + (ks + akc_l) * 2;
                ldsm_x4(aF[mt], stg + DN_A + ao);
            }
#pragma unroll
            for (int g = 0; g < 4; g++) {
                uint32_t bo = (ks + arow_l) * DN_BSTRIDE + (nwo + g * 16 + akc_l) * 2;
                uint32_t bF[4];
                ldsm_x4_t(bF, stg + DN_B + bo);
#pragma unroll
                for (int mt = 0; mt < 2; mt++)
#pragma unroll
                    for (int sub = 0; sub < 2; sub++)
                        mma16816(acc[mt][g * 2 + sub], aF[mt], bF + sub * 2);
            }
        }
    }
    CP_WAIT(0);
    __syncthreads();

    // stage C (128x128 fp32) in smem for coalesced output
    float* Cs = (float*)smem;
    int fr = lane >> 2, fc = (lane & 3) * 2;
#pragma unroll
    for (int mt = 0; mt < 2; mt++)
#pragma unroll
        for (int j = 0; j < 8; j++) {
            float* c = acc[mt][j];
            int r = mw + mt * 16 + fr, cl = nwo + j * 8 + fc;
            *(float2*)&Cs[r * 128 + cl] = make_float2(c[0], c[1]);
            *(float2*)&Cs[(r + 8) * 128 + cl] = make_float2(c[2], c[3]);
        }
    __syncthreads();

    int r = tid >> 1, cb = (tid & 1) * 64;
    if (!ROUTED) {
        float* dst = out + (size_t)(m0 + r) * DDIM + n0 + cb;
#pragma unroll
        for (int j = 0; j < 16; j++)
            ((float4*)dst)[j] = ((const float4*)&Cs[r * 128 + cb])[j];
    } else {
        int tokr = g_pair_token[m0 + r];
        if (tokr >= 0) {
            float wgt = g_pair_w[m0 + r];
            float* dst = out + (size_t)tokr * DDIM + n0 + cb;
            const float* src = &Cs[r * 128 + cb];
#pragma unroll
            for (int j = 0; j < 64; j++)
                atomicAdd(dst + j, wgt * src[j]);
        }
    }
#undef DN_ISSUE
}

// ---------------- launch ----------------
static inline void launch_cvt(const float* src, __half* dst, size_t n) {
    int n4 = (int)(n / 4);
    cvt_kernel<<<(n4 + 255) / 256, 256>>>(src, dst, n4);
}

extern "C" void kernel_launch(void* const* d_in, const int* in_sizes, int n_in,
                              void* d_out, int out_size) {
    const float* x       = (const float*)d_in[0];
    const float* Wg      = (const float*)d_in[1];
    const float* W_gate  = (const float*)d_in[2];
    const float* W_up    = (const float*)d_in[3];
    const float* W_down  = (const float*)d_in[4];
    const float* Ws_gate = (const float*)d_in[5];
    const float* Ws_up   = (const float*)d_in[6];
    const float* Ws_down = (const float*)d_in[7];
    float* out = (float*)d_out;

    cudaFuncSetAttribute(upgate_mma<false>, cudaFuncAttributeMaxDynamicSharedMemorySize, UG_SMEM);
    cudaFuncSetAttribute(upgate_mma<true>,  cudaFuncAttributeMaxDynamicSharedMemorySize, UG_SMEM);
    cudaFuncSetAttribute(down_mma<false>,   cudaFuncAttributeMaxDynamicSharedMemorySize, DN_SMEM);
    cudaFuncSetAttribute(down_mma<true>,    cudaFuncAttributeMaxDynamicSharedMemorySize, DN_SMEM);

    __half *w1, *w2, *wd, *xh;
    cudaGetSymbolAddress((void**)&w1, g_W1);
    cudaGetSymbolAddress((void**)&w2, g_W2);
    cudaGetSymbolAddress((void**)&wd, g_Wd);
    cudaGetSymbolAddress((void**)&xh, g_X);

    const size_t WSZ = (size_t)DDIM * IDIM;
    const size_t SHO = (size_t)NEXP * WSZ;

    init_kernel<<<(MAXROWS + 255) / 256, 256>>>();
    routing_kernel<<<(NTOK * 32 + 255) / 256, 256>>>(x, Wg);
    offsets_kernel<<<1, 1>>>(out, out_size);
    scatter_kernel<<<(NTOK + 255) / 256, 256>>>();

    launch_cvt(x,       xh,       (size_t)NTOK * DDIM);
    launch_cvt(W_gate,  w1,       SHO);
    launch_cvt(Ws_gate, w1 + SHO, WSZ);
    launch_cvt(W_up,    w2,       SHO);
    launch_cvt(Ws_up,   w2 + SHO, WSZ);
    launch_cvt(W_down,  wd,       SHO);
    launch_cvt(Ws_down, wd + SHO, WSZ);

    // shared expert (e=8)
    upgate_mma<false><<<dim3(IDIM / 64, NTOK / BM), 256, UG_SMEM>>>();
    down_mma<false><<<dim3(DDIM / 128, NTOK / BM), 256, DN_SMEM>>>(out);

    // routed experts (expert-sorted, 128-padded segments)
    upgate_mma<true><<<dim3(IDIM / 64, NTILES), 256, UG_SMEM>>>();
    down_mma<true><<<dim3(DDIM / 128, NTILES), 256, DN_SMEM>>>(out);
}

// round 6
// speedup vs baseline: 5.6107x; 1.1124x over previous
#include <cuda_runtime.h>
#include <cuda_fp16.h>
#include <math.h>
#include <stdint.h>

// Problem constants (B=2, S=2048 -> N=4096 tokens)
#define NTOK 4096
#define DDIM 1024
#define IDIM 2048
#define NEXP 8
#define TOPK 2
#define BM   128
#define MAXROWS 9216
#define NTILES  72
#define NSHARED_TILES (NTOK / BM)   // 32
#define GROWS (MAXROWS + NTOK)      // routed rows [0,MAXROWS), shared rows [MAXROWS, ...)

// ---------------- scratch (device globals) ----------------
__device__ __align__(16) __half g_W1[(size_t)9 * DDIM * IDIM];
__device__ __align__(16) __half g_W2[(size_t)9 * DDIM * IDIM];
__device__ __align__(16) __half g_Wd[(size_t)9 * IDIM * DDIM];
__device__ __align__(16) __half g_X[(size_t)NTOK * DDIM];
__device__ __align__(16) __half g_Gf[(size_t)GROWS * IDIM];

__device__ int   g_topk_idx[NTOK * TOPK];
__device__ float g_topk_w[NTOK * TOPK];
__device__ int   g_cnt[NEXP];
__device__ float g_Psum[NEXP];
__device__ int   g_cursor[NEXP];
__device__ int   g_off[NEXP + 1];
__device__ int   g_pair_token[MAXROWS];
__device__ float g_pair_w[MAXROWS];
__device__ int   g_tile_expert[NTILES];

// ---------------- helpers ----------------
__device__ __forceinline__ uint32_t smem_u32(const void* p) {
    uint32_t a;
    asm("{ .reg .u64 t; cvta.to.shared.u64 t, %1; cvt.u32.u64 %0, t; }" : "=r"(a) : "l"(p));
    return a;
}
__device__ __forceinline__ void ldsm_x4(uint32_t* r, uint32_t addr) {
    asm volatile("ldmatrix.sync.aligned.m8n8.x4.shared.b16 {%0,%1,%2,%3}, [%4];"
                 : "=r"(r[0]), "=r"(r[1]), "=r"(r[2]), "=r"(r[3]) : "r"(addr));
}
__device__ __forceinline__ void ldsm_x4_t(uint32_t* r, uint32_t addr) {
    asm volatile("ldmatrix.sync.aligned.m8n8.x4.trans.shared.b16 {%0,%1,%2,%3}, [%4];"
                 : "=r"(r[0]), "=r"(r[1]), "=r"(r[2]), "=r"(r[3]) : "r"(addr));
}
__device__ __forceinline__ void mma16816(float* c, const uint32_t* a, const uint32_t* b) {
    asm volatile("mma.sync.aligned.m16n8k16.row.col.f32.f16.f16.f32 "
                 "{%0,%1,%2,%3}, {%4,%5,%6,%7}, {%8,%9}, {%0,%1,%2,%3};"
                 : "+f"(c[0]), "+f"(c[1]), "+f"(c[2]), "+f"(c[3])
                 : "r"(a[0]), "r"(a[1]), "r"(a[2]), "r"(a[3]), "r"(b[0]), "r"(b[1]));
}
__device__ __forceinline__ void cpa16(uint32_t dst, const void* src, uint32_t srcsz) {
    asm volatile("cp.async.cg.shared.global [%0], [%1], 16, %2;"
                 :: "r"(dst), "l"(src), "r"(srcsz) : "memory");
}
#define CP_COMMIT() asm volatile("cp.async.commit_group;" ::: "memory")
#define CP_WAIT(n)  asm volatile("cp.async.wait_group %0;" :: "n"(n) : "memory")
__device__ __forceinline__ void red_add_v4(float* p, float a, float b, float c, float d) {
    asm volatile("red.global.add.v4.f32 [%0], {%1,%2,%3,%4};"
                 :: "l"(p), "f"(a), "f"(b), "f"(c), "f"(d) : "memory");
}

// ---------------- fused convert: fp32 -> fp16, all tensors, one launch ----------------
__global__ void cvt_all_kernel(const float* __restrict__ x,
                               const float* __restrict__ W_gate, const float* __restrict__ Ws_gate,
                               const float* __restrict__ W_up,   const float* __restrict__ Ws_up,
                               const float* __restrict__ W_down, const float* __restrict__ Ws_down) {
    const long RX = (long)NTOK * DDIM / 4;
    const long RW = (long)NEXP * DDIM * IDIM / 4;
    const long RS = (long)DDIM * IDIM / 4;
    const long SHOe = (long)NEXP * DDIM * IDIM;  // element offset of shared expert
    long i = (long)blockIdx.x * blockDim.x + threadIdx.x;
    const float* src; __half* dst; long o;
    if (i < RX)                 { src = x;       dst = g_X;               o = i; }
    else if ((i -= RX) < RW)    { src = W_gate;  dst = g_W1;              o = i; }
    else if ((i -= RW) < RS)    { src = Ws_gate; dst = g_W1 + SHOe;       o = i; }
    else if ((i -= RS) < RW)    { src = W_up;    dst = g_W2;              o = i; }
    else if ((i -= RW) < RS)    { src = Ws_up;   dst = g_W2 + SHOe;       o = i; }
    else if ((i -= RS) < RW)    { src = W_down;  dst = g_Wd;              o = i; }
    else if ((i -= RW) < RS)    { src = Ws_down; dst = g_Wd + SHOe;       o = i; }
    else return;
    float4 v = ((const float4*)src)[o];
    __half2 h0 = __floats2half2_rn(v.x, v.y);
    __half2 h1 = __floats2half2_rn(v.z, v.w);
    uint2 w;
    w.x = *reinterpret_cast<uint32_t*>(&h0);
    w.y = *reinterpret_cast<uint32_t*>(&h1);
    ((uint2*)dst)[o] = w;
}
#define CVT_TOTAL_F4 ((long)NTOK * DDIM / 4 + 3 * ((long)NEXP * DDIM * IDIM / 4 + (long)DDIM * IDIM / 4))

// ---------------- small kernels ----------------
__global__ void init_kernel() {
    int i = blockIdx.x * blockDim.x + threadIdx.x;
    if (i < NEXP) { g_cnt[i] = 0; g_Psum[i] = 0.f; g_cursor[i] = 0; }
    if (i < MAXROWS) { g_pair_token[i] = -1; g_pair_w[i] = 0.f; }
}

__global__ void routing_kernel(const float* __restrict__ x, const float* __restrict__ Wg) {
    int gwarp = (blockIdx.x * blockDim.x + threadIdx.x) >> 5;
    int lane = threadIdx.x & 31;
    if (gwarp >= NTOK) return;
    const float* xr = x + (size_t)gwarp * DDIM;
    float acc[NEXP];
#pragma unroll
    for (int e = 0; e < NEXP; e++) acc[e] = 0.f;
    for (int j = lane; j < DDIM; j += 32) {
        float xv = xr[j];
        const float* wr = Wg + (size_t)j * NEXP;
#pragma unroll
        for (int e = 0; e < NEXP; e++) acc[e] = fmaf(xv, wr[e], acc[e]);
    }
#pragma unroll
    for (int e = 0; e < NEXP; e++) {
#pragma unroll
        for (int o = 16; o; o >>= 1) acc[e] += __shfl_xor_sync(0xffffffffu, acc[e], o);
    }
    float mx = acc[0];
#pragma unroll
    for (int e = 1; e < NEXP; e++) mx = fmaxf(mx, acc[e]);
    float p[NEXP], s = 0.f;
#pragma unroll
    for (int e = 0; e < NEXP; e++) { p[e] = expf(acc[e] - mx); s += p[e]; }
    float invs = 1.f / s;
#pragma unroll
    for (int e = 0; e < NEXP; e++) p[e] *= invs;
    if (lane < NEXP) atomicAdd(&g_Psum[lane], p[lane]);
    if (lane == 0) {
        int i0 = 0;
#pragma unroll
        for (int e = 1; e < NEXP; e++) if (p[e] > p[i0]) i0 = e;
        int i1 = (i0 == 0) ? 1 : 0;
#pragma unroll
        for (int e = 0; e < NEXP; e++) if (e != i0 && p[e] > p[i1]) i1 = e;
        float w0 = p[i0], w1 = p[i1];
        float inv = 1.f / (w0 + w1 + 1e-9f);
        g_topk_idx[gwarp * 2 + 0] = i0;
        g_topk_idx[gwarp * 2 + 1] = i1;
        g_topk_w[gwarp * 2 + 0] = w0 * inv;
        g_topk_w[gwarp * 2 + 1] = w1 * inv;
        atomicAdd(&g_cnt[i0], 1);
        atomicAdd(&g_cnt[i1], 1);
    }
}

// parallel offsets + tile map + aux loss (1 block, 256 threads)
__global__ void offsets_kernel(float* __restrict__ out, int out_size) {
    __shared__ int soff[NEXP + 1];
    int tid = threadIdx.x;
    if (tid == 0) {
        int acc = 0;
        soff[0] = 0;
        for (int e = 0; e < NEXP; e++) {
            acc += ((g_cnt[e] + BM - 1) / BM) * BM;
            soff[e + 1] = acc;
        }
#pragma unroll
        for (int e = 0; e <= NEXP; e++) g_off[e] = soff[e];
    }
    __syncthreads();
    if (tid < NTILES) {
        int r = tid * BM, te = 0;
#pragma unroll
        for (int e = 0; e < NEXP; e++)
            if (r >= soff[e] && r < soff[e + 1]) te = e;
        g_tile_expert[tid] = te;
    }
    if (tid < 32) {
        float term = 0.f;
        if (tid < NEXP) {
            float f = (float)g_cnt[tid] / ((float)(NTOK * TOPK) + 1e-9f);
            float P = g_Psum[tid] / (float)NTOK;
            term = f * P;
        }
#pragma unroll
        for (int o = 16; o; o >>= 1) term += __shfl_xor_sync(0xffffffffu, term, o);
        if (tid == 0) out[out_size - 1] = 0.01f * (float)NEXP * term;
    }
}

__global__ void scatter_kernel() {
    int n = blockIdx.x * blockDim.x + threadIdx.x;
    if (n >= NTOK) return;
#pragma unroll
    for (int k = 0; k < TOPK; k++) {
        int e = g_topk_idx[n * 2 + k];
        int slot = g_off[e] + atomicAdd(&g_cursor[e], 1);
        g_pair_token[slot] = n;
        g_pair_w[slot] = g_topk_w[n * 2 + k];
    }
}

// ---------------- SMEM layout (fp16 tiles, 4-stage pipeline) ----------------
#define STAGES 4
#define A_STRIDE 80
#define A_BYTES  (128 * A_STRIDE)           // 10240
#define UG_BSTRIDE 144
#define UG_BBYTES  (32 * UG_BSTRIDE)        // 4608
#define UG_A  0
#define UG_BG A_BYTES
#define UG_BU (UG_BG + UG_BBYTES)
#define UG_STAGE (UG_BU + UG_BBYTES)        // 19456
#define UG_SMEM (STAGES * UG_STAGE)         // 77824

#define DN_BSTRIDE 272
#define DN_BBYTES  (32 * DN_BSTRIDE)        // 8704
#define DN_A  0
#define DN_B  A_BYTES
#define DN_STAGE (DN_B + DN_BBYTES)         // 18944
#define DN_SMEM (STAGES * DN_STAGE)         // 75776

// ---------------- merged up/gate GEMM + SiLU (shared + routed in one grid) ----------------
// grid: (IDIM/64, NSHARED_TILES + NTILES). by < NSHARED_TILES => shared expert.
__global__ void __launch_bounds__(256)
upgate_all() {
    extern __shared__ char smem[];
    uint32_t sb = smem_u32(smem);
    int tid = threadIdx.x;
    int wid = tid >> 5, lane = tid & 31;
    int by = blockIdx.y, n0 = blockIdx.x * 64;

    bool routed = (by >= NSHARED_TILES);
    int m0, gbase, e;
    if (!routed) { m0 = by * BM; gbase = MAXROWS + m0; e = NEXP; }
    else {
        int t = by - NSHARED_TILES;
        m0 = t * BM;
        if (m0 >= g_off[NEXP]) return;
        gbase = m0;
        e = g_tile_expert[t];
    }

    const __half* w1 = g_W1 + (size_t)e * DDIM * IDIM;
    const __half* w2 = g_W2 + (size_t)e * DDIM * IDIM;

    int r0 = tid >> 2, kq = (tid & 3) * 8;
    int r1 = r0 + 64;
    int t0 = routed ? g_pair_token[m0 + r0] : (m0 + r0);
    int t1 = routed ? g_pair_token[m0 + r1] : (m0 + r1);
    uint32_t sz0 = (t0 >= 0) ? 16u : 0u;
    uint32_t sz1 = (t1 >= 0) ? 16u : 0u;
    const __half* a0 = g_X + (size_t)(t0 >= 0 ? t0 : 0) * DDIM + kq;
    const __half* a1 = g_X + (size_t)(t1 >= 0 ? t1 : 0) * DDIM + kq;
    uint32_t dA0 = UG_A + (uint32_t)(r0 * A_STRIDE + kq * 2);
    uint32_t dA1 = UG_A + (uint32_t)(r1 * A_STRIDE + kq * 2);
    int br = tid >> 3, bn = (tid & 7) * 8;
    uint32_t dB = (uint32_t)(br * UG_BSTRIDE + bn * 2);
    size_t bsrc0 = (size_t)br * IDIM + n0 + bn;

    const int NST = DDIM / 32;  // 32

#define UG_ISSUE(s_) do { \
        uint32_t st = sb + (uint32_t)(((s_) % STAGES) * UG_STAGE); \
        int k0 = (s_) * 32; \
        cpa16(st + dA0, a0 + k0, sz0); \
        cpa16(st + dA1, a1 + k0, sz1); \
        size_t bo = bsrc0 + (size_t)k0 * IDIM; \
        cpa16(st + UG_BG + dB, w1 + bo, 16u); \
        cpa16(st + UG_BU + dB, w2 + bo, 16u); \
    } while (0)

    UG_ISSUE(0); CP_COMMIT();
    UG_ISSUE(1); CP_COMMIT();
    UG_ISSUE(2); CP_COMMIT();

    int arow_l = (lane & 7) + ((lane >> 3) & 1) * 8;
    int akc_l = (lane >> 4) * 8;
    int mw = (wid & 3) * 32;
    bool isGate = (wid < 4);
    uint32_t bBase = isGate ? UG_BG : UG_BU;

    float acc[2][8][4];
#pragma unroll
    for (int i = 0; i < 2; i++)
#pragma unroll
        for (int j = 0; j < 8; j++)
#pragma unroll
            for (int q = 0; q < 4; q++) acc[i][j][q] = 0.f;

    for (int s = 0; s < NST; s++) {
        CP_WAIT(2);
        __syncthreads();
        if (s + 3 < NST) UG_ISSUE(s + 3);
        CP_COMMIT();
        uint32_t stg = sb + (uint32_t)((s % STAGES) * UG_STAGE);
#pragma unroll
        for (int ks = 0; ks < 32; ks += 16) {
            uint32_t aF[2][4];
#pragma unroll
            for (int mt = 0; mt < 2; mt++) {
                uint32_t ao = (mw + mt * 16 + arow_l) * A_STRIDE + (ks + akc_l) * 2;
                ldsm_x4(aF[mt], stg + UG_A + ao);
            }
#pragma unroll
            for (int g = 0; g < 4; g++) {
                uint32_t bo = (ks + arow_l) * UG_BSTRIDE + (g * 16 + akc_l) * 2;
                uint32_t bF[4];
                ldsm_x4_t(bF, stg + bBase + bo);
#pragma unroll
                for (int mt = 0; mt < 2; mt++)
#pragma unroll
                    for (int sub = 0; sub < 2; sub++)
                        mma16816(acc[mt][g * 2 + sub], aF[mt], bF + sub * 2);
            }
        }
    }
    CP_WAIT(0);
    __syncthreads();

    // epilogue: exchange up via smem, SiLU, write G fp16
    float* exch = (float*)smem;
    int fr = lane >> 2, fc = (lane & 3) * 2;
    if (!isGate) {
#pragma unroll
        for (int mt = 0; mt < 2; mt++)
#pragma unroll
            for (int j = 0; j < 8; j++) {
                float* c = acc[mt][j];
                int r = mw + mt * 16 + fr, cl = j * 8 + fc;
                *(float2*)&exch[r * 64 + cl] = make_float2(c[0], c[1]);
                *(float2*)&exch[(r + 8) * 64 + cl] = make_float2(c[2], c[3]);
            }
    }
    __syncthreads();
    if (isGate) {
#pragma unroll
        for (int mt = 0; mt < 2; mt++)
#pragma unroll
            for (int j = 0; j < 8; j++) {
                float* c = acc[mt][j];
                int r = mw + mt * 16 + fr, cl = j * 8 + fc;
                float2 u0 = *(float2*)&exch[r * 64 + cl];
                float2 u1 = *(float2*)&exch[(r + 8) * 64 + cl];
                float2 g0, g1;
                g0.x = c[0] / (1.f + __expf(-c[0])) * u0.x;
                g0.y = c[1] / (1.f + __expf(-c[1])) * u0.y;
                g1.x = c[2] / (1.f + __expf(-c[2])) * u1.x;
                g1.y = c[3] / (1.f + __expf(-c[3])) * u1.y;
                *(float2*)&exch[r * 64 + cl] = g0;
                *(float2*)&exch[(r + 8) * 64 + cl] = g1;
            }
    }
    __syncthreads();
    {
        int r = tid >> 1, cb = (tid & 1) * 32;
        const float4* src = (const float4*)&exch[r * 64 + cb];
        __half* dst = g_Gf + (size_t)(gbase + r) * IDIM + n0 + cb;
#pragma unroll
        for (int j = 0; j < 8; j++) {
            float4 v = src[j];
            __half2 h0 = __floats2half2_rn(v.x, v.y);
            __half2 h1 = __floats2half2_rn(v.z, v.w);
            uint2 o;
            o.x = *reinterpret_cast<uint32_t*>(&h0);
            o.y = *reinterpret_cast<uint32_t*>(&h1);
            ((uint2*)dst)[j] = o;
        }
    }
#undef UG_ISSUE
}

// ---------------- merged down GEMM (shared + routed; out zero-initialized, red.add) ---------
__global__ void __launch_bounds__(256)
down_all(float* __restrict__ out) {
    extern __shared__ char smem[];
    uint32_t sb = smem_u32(smem);
    int tid = threadIdx.x;
    int wid = tid >> 5, lane = tid & 31;
    int by = blockIdx.y, n0 = blockIdx.x * 128;

    bool routed = (by >= NSHARED_TILES);
    int m0, gbase, e;
    if (!routed) { m0 = by * BM; gbase = MAXROWS + m0; e = NEXP; }
    else {
        int t = by - NSHARED_TILES;
        m0 = t * BM;
        if (m0 >= g_off[NEXP]) return;
        gbase = m0;
        e = g_tile_expert[t];
    }

    const __half* w = g_Wd + (size_t)e * IDIM * DDIM;

    int r0 = tid >> 2, kq = (tid & 3) * 8;
    int r1 = r0 + 64;
    const __half* a0 = g_Gf + (size_t)(gbase + r0) * IDIM + kq;
    const __half* a1 = g_Gf + (size_t)(gbase + r1) * IDIM + kq;
    uint32_t dA0 = DN_A + (uint32_t)(r0 * A_STRIDE + kq * 2);
    uint32_t dA1 = DN_A + (uint32_t)(r1 * A_STRIDE + kq * 2);
    int br0 = tid >> 4, bnc = (tid & 15) * 8;
    int br1 = br0 + 16;
    uint32_t dB0 = (uint32_t)(br0 * DN_BSTRIDE + bnc * 2);
    uint32_t dB1 = (uint32_t)(br1 * DN_BSTRIDE + bnc * 2);
    size_t bs0 = (size_t)br0 * DDIM + n0 + bnc;
    size_t bs1 = (size_t)br1 * DDIM + n0 + bnc;

    const int NST = IDIM / 32;  // 64

#define DN_ISSUE(s_) do { \
        uint32_t st = sb + (uint32_t)(((s_) % STAGES) * DN_STAGE); \
        int k0 = (s_) * 32; \
        cpa16(st + dA0, a0 + k0, 16u); \
        cpa16(st + dA1, a1 + k0, 16u); \
        size_t o0 = bs0 + (size_t)k0 * DDIM, o1 = bs1 + (size_t)k0 * DDIM; \
        cpa16(st + DN_B + dB0, w + o0, 16u); \
        cpa16(st + DN_B + dB1, w + o1, 16u); \
    } while (0)

    DN_ISSUE(0); CP_COMMIT();
    DN_ISSUE(1); CP_COMMIT();
    DN_ISSUE(2); CP_COMMIT();

    int arow_l = (lane & 7) + ((lane >> 3) & 1) * 8;
    int akc_l = (lane >> 4) * 8;
    int mw = (wid >> 1) * 32;
    int nwo = (wid & 1) * 64;

    float acc[2][8][4];
#pragma unroll
    for (int i = 0; i < 2; i++)
#pragma unroll
        for (int j = 0; j < 8; j++)
#pragma unroll
            for (int q = 0; q < 4; q++) acc[i][j][q] = 0.f;

    for (int s = 0; s < NST; s++) {
        CP_WAIT(2);
        __syncthreads();
        if (s + 3 < NST) DN_ISSUE(s + 3);
        CP_COMMIT();
        uint32_t stg = sb + (uint32_t)((s % STAGES) * DN_STAGE);
#pragma unroll
        for (int ks = 0; ks < 32; ks += 16) {
            uint32_t aF[2][4];
#pragma unroll
            for (int mt = 0; mt < 2; mt++) {
                uint32_t ao = (mw + mt * 16 + arow_l) * A_STRIDE + (ks + akc_l) * 2;
                ldsm_x4(aF[mt], stg + DN_A + ao);
            }
#pragma unroll
            for (int g = 0; g < 4; g++) {
                uint32_t bo = (ks + arow_l) * DN_BSTRIDE + (nwo + g * 16 + akc_l) * 2;
                uint32_t bF[4];
                ldsm_x4_t(bF, stg + DN_B + bo);
#pragma unroll
                for (int mt = 0; mt < 2; mt++)
#pragma unroll
                    for (int sub = 0; sub < 2; sub++)
                        mma16816(acc[mt][g * 2 + sub], aF[mt], bF + sub * 2);
            }
        }
    }
    CP_WAIT(0);
    __syncthreads();

    // stage C (128x128 fp32) in smem, then red.add.v4 into zero-initialized out
    float* Cs = (float*)smem;
    int fr = lane >> 2, fc = (lane & 3) * 2;
#pragma unroll
    for (int mt = 0; mt < 2; mt++)
#pragma unroll
        for (int j = 0; j < 8; j++) {
            float* c = acc[mt][j];
            int r = mw + mt * 16 + fr, cl = nwo + j * 8 + fc;
            *(float2*)&Cs[r * 128 + cl] = make_float2(c[0], c[1]);
            *(float2*)&Cs[(r + 8) * 128 + cl] = make_float2(c[2], c[3]);
        }
    __syncthreads();

    int r = tid >> 1, cb = (tid & 1) * 64;
    int tokr = routed ? g_pair_token[m0 + r] : (m0 + r);
    if (tokr >= 0) {
        float wgt = routed ? g_pair_w[m0 + r] : 1.f;
        float* dst = out + (size_t)tokr * DDIM + n0 + cb;
        const float* src = &Cs[r * 128 + cb];
#pragma unroll
        for (int j = 0; j < 16; j++)
            red_add_v4(dst + j * 4, wgt * src[j * 4 + 0], wgt * src[j * 4 + 1],
                       wgt * src[j * 4 + 2], wgt * src[j * 4 + 3]);
    }
#undef DN_ISSUE
}

// ---------------- launch ----------------
extern "C" void kernel_launch(void* const* d_in, const int* in_sizes, int n_in,
                              void* d_out, int out_size) {
    const float* x       = (const float*)d_in[0];
    const float* Wg      = (const float*)d_in[1];
    const float* W_gate  = (const float*)d_in[2];
    const float* W_up    = (const float*)d_in[3];
    const float* W_down  = (const float*)d_in[4];
    const float* Ws_gate = (const float*)d_in[5];
    const float* Ws_up   = (const float*)d_in[6];
    const float* Ws_down = (const float*)d_in[7];
    float* out = (float*)d_out;

    cudaFuncSetAttribute(upgate_all, cudaFuncAttributeMaxDynamicSharedMemorySize, UG_SMEM);
    cudaFuncSetAttribute(down_all,   cudaFuncAttributeMaxDynamicSharedMemorySize, DN_SMEM);

    // zero the output (graph-capturable memset node); aux + all FFN adds land on zeros
    cudaMemsetAsync(out, 0, (size_t)out_size * sizeof(float));

    init_kernel<<<(MAXROWS + 255) / 256, 256>>>();
    routing_kernel<<<(NTOK * 32 + 255) / 256, 256>>>(x, Wg);
    offsets_kernel<<<1, 256>>>(out, out_size);
    scatter_kernel<<<(NTOK + 255) / 256, 256>>>();
    {
        long n4 = CVT_TOTAL_F4;
        cvt_all_kernel<<<(int)((n4 + 255) / 256), 256>>>(x, W_gate, Ws_gate, W_up, Ws_up, W_down, Ws_down);
    }

    // merged GEMMs: shared tiles [0,32) + routed tiles [32, 32+NTILES)
    upgate_all<<<dim3(IDIM / 64, NSHARED_TILES + NTILES), 256, UG_SMEM>>>();
    down_all<<<dim3(DDIM / 128, NSHARED_TILES + NTILES), 256, DN_SMEM>>>(out);
}

// round 7
// speedup vs baseline: 5.6336x; 1.0041x over previous
#include <cuda_runtime.h>
#include <cuda_fp16.h>
#include <math.h>
#include <stdint.h>

// Problem constants (B=2, S=2048 -> N=4096 tokens)
#define NTOK 4096
#define DDIM 1024
#define IDIM 2048
#define NEXP 8
#define TOPK 2
#define BM   128
#define MAXROWS 9216
#define NTILES  72
#define NSHARED_TILES (NTOK / BM)   // 32
#define GROWS (MAXROWS + NTOK)

// ---------------- scratch (device globals) ----------------
__device__ __align__(16) __half g_W1[(size_t)9 * DDIM * IDIM];
__device__ __align__(16) __half g_W2[(size_t)9 * DDIM * IDIM];
__device__ __align__(16) __half g_Wd[(size_t)9 * IDIM * DDIM];
__device__ __align__(16) __half g_X[(size_t)NTOK * DDIM];
__device__ __align__(16) __half g_Gf[(size_t)GROWS * IDIM];

__device__ int   g_topk_idx[NTOK * TOPK];
__device__ float g_topk_w[NTOK * TOPK];
__device__ float g_probs[NTOK * NEXP];
__device__ int   g_cursor[NEXP];
__device__ int   g_off[NEXP + 1];
__device__ int   g_pair_token[MAXROWS];
__device__ float g_pair_w[MAXROWS];
__device__ int   g_tile_expert[NTILES];

// ---------------- helpers ----------------
__device__ __forceinline__ uint32_t smem_u32(const void* p) {
    uint32_t a;
    asm("{ .reg .u64 t; cvta.to.shared.u64 t, %1; cvt.u32.u64 %0, t; }" : "=r"(a) : "l"(p));
    return a;
}
__device__ __forceinline__ void ldsm_x4(uint32_t* r, uint32_t addr) {
    asm volatile("ldmatrix.sync.aligned.m8n8.x4.shared.b16 {%0,%1,%2,%3}, [%4];"
                 : "=r"(r[0]), "=r"(r[1]), "=r"(r[2]), "=r"(r[3]) : "r"(addr));
}
__device__ __forceinline__ void ldsm_x4_t(uint32_t* r, uint32_t addr) {
    asm volatile("ldmatrix.sync.aligned.m8n8.x4.trans.shared.b16 {%0,%1,%2,%3}, [%4];"
                 : "=r"(r[0]), "=r"(r[1]), "=r"(r[2]), "=r"(r[3]) : "r"(addr));
}
__device__ __forceinline__ void mma16816(float* c, const uint32_t* a, const uint32_t* b) {
    asm volatile("mma.sync.aligned.m16n8k16.row.col.f32.f16.f16.f32 "
                 "{%0,%1,%2,%3}, {%4,%5,%6,%7}, {%8,%9}, {%0,%1,%2,%3};"
                 : "+f"(c[0]), "+f"(c[1]), "+f"(c[2]), "+f"(c[3])
                 : "r"(a[0]), "r"(a[1]), "r"(a[2]), "r"(a[3]), "r"(b[0]), "r"(b[1]));
}
__device__ __forceinline__ void cpa16(uint32_t dst, const void* src, uint32_t srcsz) {
    asm volatile("cp.async.cg.shared.global [%0], [%1], 16, %2;"
                 :: "r"(dst), "l"(src), "r"(srcsz) : "memory");
}
#define CP_COMMIT() asm volatile("cp.async.commit_group;" ::: "memory")
#define CP_WAIT(n)  asm volatile("cp.async.wait_group %0;" :: "n"(n) : "memory")
__device__ __forceinline__ void red_add_v4(float* p, float a, float b, float c, float d) {
    asm volatile("red.global.add.v4.f32 [%0], {%1,%2,%3,%4};"
                 :: "l"(p), "f"(a), "f"(b), "f"(c), "f"(d) : "memory");
}

// ---------------- prep: routing + init + fp32->fp16 convert, one launch -------
#define RX_F4 ((long)NTOK * DDIM / 4)
#define RW_F4 ((long)NEXP * DDIM * IDIM / 4)
#define RS_F4 ((long)DDIM * IDIM / 4)
#define CVT_TOTAL_F4 (RX_F4 + 3 * (RW_F4 + RS_F4))
#define NB_ROUTE 512                                   // 4096 warps
#define NB_INIT  ((MAXROWS + 255) / 256)               // 36
#define NB_CVT   ((int)((CVT_TOTAL_F4 + 255) / 256))
#define NB_PREP  (NB_ROUTE + NB_INIT + NB_CVT)

__global__ void prep_kernel(const float* __restrict__ x, const float* __restrict__ Wg,
                            const float* __restrict__ W_gate, const float* __restrict__ Ws_gate,
                            const float* __restrict__ W_up,   const float* __restrict__ Ws_up,
                            const float* __restrict__ W_down, const float* __restrict__ Ws_down) {
    int bid = blockIdx.x;
    if (bid < NB_ROUTE) {
        // ---- routing: one warp per token; no global atomics (offsets scans later)
        int gwarp = (bid * 256 + threadIdx.x) >> 5;
        int lane = threadIdx.x & 31;
        const float* xr = x + (size_t)gwarp * DDIM;
        float acc[NEXP];
#pragma unroll
        for (int e = 0; e < NEXP; e++) acc[e] = 0.f;
        for (int j = lane; j < DDIM; j += 32) {
            float xv = xr[j];
            const float* wr = Wg + (size_t)j * NEXP;
#pragma unroll
            for (int e = 0; e < NEXP; e++) acc[e] = fmaf(xv, wr[e], acc[e]);
        }
#pragma unroll
        for (int e = 0; e < NEXP; e++) {
#pragma unroll
            for (int o = 16; o; o >>= 1) acc[e] += __shfl_xor_sync(0xffffffffu, acc[e], o);
        }
        float mx = acc[0];
#pragma unroll
        for (int e = 1; e < NEXP; e++) mx = fmaxf(mx, acc[e]);
        float p[NEXP], s = 0.f;
#pragma unroll
        for (int e = 0; e < NEXP; e++) { p[e] = expf(acc[e] - mx); s += p[e]; }
        float invs = 1.f / s;
#pragma unroll
        for (int e = 0; e < NEXP; e++) p[e] *= invs;
        if (lane < NEXP) g_probs[gwarp * NEXP + lane] = p[lane];
        if (lane == 0) {
            int i0 = 0;
#pragma unroll
            for (int e = 1; e < NEXP; e++) if (p[e] > p[i0]) i0 = e;
            int i1 = (i0 == 0) ? 1 : 0;
#pragma unroll
            for (int e = 0; e < NEXP; e++) if (e != i0 && p[e] > p[i1]) i1 = e;
            float w0 = p[i0], w1 = p[i1];
            float inv = 1.f / (w0 + w1 + 1e-9f);
            g_topk_idx[gwarp * 2 + 0] = i0;
            g_topk_idx[gwarp * 2 + 1] = i1;
            g_topk_w[gwarp * 2 + 0] = w0 * inv;
            g_topk_w[gwarp * 2 + 1] = w1 * inv;
        }
        return;
    }
    bid -= NB_ROUTE;
    if (bid < NB_INIT) {
        int i = bid * 256 + threadIdx.x;
        if (i < NEXP) g_cursor[i] = 0;
        if (i < MAXROWS) { g_pair_token[i] = -1; g_pair_w[i] = 0.f; }
        return;
    }
    bid -= NB_INIT;
    // ---- convert fp32 -> fp16 (region dispatch)
    long i = (long)bid * 256 + threadIdx.x;
    const long SHOe = (long)NEXP * DDIM * IDIM;
    const float* src; __half* dst; long o;
    if (i < RX_F4)                  { src = x;       dst = g_X;         o = i; }
    else if ((i -= RX_F4) < RW_F4)  { src = W_gate;  dst = g_W1;        o = i; }
    else if ((i -= RW_F4) < RS_F4)  { src = Ws_gate; dst = g_W1 + SHOe; o = i; }
    else if ((i -= RS_F4) < RW_F4)  { src = W_up;    dst = g_W2;        o = i; }
    else if ((i -= RW_F4) < RS_F4)  { src = Ws_up;   dst = g_W2 + SHOe; o = i; }
    else if ((i -= RS_F4) < RW_F4)  { src = W_down;  dst = g_Wd;        o = i; }
    else if ((i -= RW_F4) < RS_F4)  { src = Ws_down; dst = g_Wd + SHOe; o = i; }
    else return;
    float4 v = ((const float4*)src)[o];
    __half2 h0 = __floats2half2_rn(v.x, v.y);
    __half2 h1 = __floats2half2_rn(v.z, v.w);
    uint2 w;
    w.x = *reinterpret_cast<uint32_t*>(&h0);
    w.y = *reinterpret_cast<uint32_t*>(&h1);
    ((uint2*)dst)[o] = w;
}

// ---------------- offsets: counts + Psum from scans, tile map, aux (1 block) ---
__global__ void offsets_kernel(float* __restrict__ out, int out_size) {
    __shared__ int scnt[NEXP];
    __shared__ float sP[NEXP];
    __shared__ int soff[NEXP + 1];
    int tid = threadIdx.x;
    if (tid < NEXP) { scnt[tid] = 0; sP[tid] = 0.f; }
    __syncthreads();
    for (int i = tid; i < NTOK * TOPK; i += 256)
        atomicAdd(&scnt[g_topk_idx[i]], 1);
    {
        float ps[NEXP];
#pragma unroll
        for (int e = 0; e < NEXP; e++) ps[e] = 0.f;
        for (int i = tid; i < NTOK; i += 256) {
            const float* pr = g_probs + i * NEXP;
#pragma unroll
            for (int e = 0; e < NEXP; e++) ps[e] += pr[e];
        }
#pragma unroll
        for (int e = 0; e < NEXP; e++) atomicAdd(&sP[e], ps[e]);
    }
    __syncthreads();
    if (tid == 0) {
        int acc = 0;
        soff[0] = 0;
        for (int e = 0; e < NEXP; e++) {
            acc += ((scnt[e] + BM - 1) / BM) * BM;
            soff[e + 1] = acc;
        }
#pragma unroll
        for (int e = 0; e <= NEXP; e++) g_off[e] = soff[e];
    }
    __syncthreads();
    if (tid < NTILES) {
        int r = tid * BM, te = 0;
#pragma unroll
        for (int e = 0; e < NEXP; e++)
            if (r >= soff[e] && r < soff[e + 1]) te = e;
        g_tile_expert[tid] = te;
    }
    if (tid < 32) {
        float term = 0.f;
        if (tid < NEXP) {
            float f = (float)scnt[tid] / ((float)(NTOK * TOPK) + 1e-9f);
            float P = sP[tid] / (float)NTOK;
            term = f * P;
        }
#pragma unroll
        for (int o = 16; o; o >>= 1) term += __shfl_xor_sync(0xffffffffu, term, o);
        if (tid == 0) out[out_size - 1] = 0.01f * (float)NEXP * term;
    }
}

__global__ void scatter_kernel() {
    int n = blockIdx.x * blockDim.x + threadIdx.x;
    if (n >= NTOK) return;
#pragma unroll
    for (int k = 0; k < TOPK; k++) {
        int e = g_topk_idx[n * 2 + k];
        int slot = g_off[e] + atomicAdd(&g_cursor[e], 1);
        g_pair_token[slot] = n;
        g_pair_w[slot] = g_topk_w[n * 2 + k];
    }
}

// ---------------- SMEM layout (fp16 tiles, 4-stage pipeline) ----------------
#define STAGES 4
#define A_STRIDE 80
#define A_BYTES  (128 * A_STRIDE)           // 10240
#define UG_BSTRIDE 144
#define UG_BBYTES  (32 * UG_BSTRIDE)        // 4608
#define UG_A  0
#define UG_BG A_BYTES
#define UG_BU (UG_BG + UG_BBYTES)
#define UG_STAGE (UG_BU + UG_BBYTES)        // 19456
#define UG_SMEM (STAGES * UG_STAGE)         // 77824

#define DN_BSTRIDE 272
#define DN_BBYTES  (32 * DN_BSTRIDE)        // 8704
#define DN_A  0
#define DN_B  A_BYTES
#define DN_STAGE (DN_B + DN_BBYTES)         // 18944
#define DN_SMEM (STAGES * DN_STAGE)         // 75776

// ---------------- merged up/gate GEMM + SiLU ----------------
__global__ void __launch_bounds__(256, 2)
upgate_all() {
    extern __shared__ char smem[];
    uint32_t sb = smem_u32(smem);
    int tid = threadIdx.x;
    int wid = tid >> 5, lane = tid & 31;
    int by = blockIdx.y, n0 = blockIdx.x * 64;

    bool routed = (by >= NSHARED_TILES);
    int m0, gbase, e;
    if (!routed) { m0 = by * BM; gbase = MAXROWS + m0; e = NEXP; }
    else {
        int t = by - NSHARED_TILES;
        m0 = t * BM;
        if (m0 >= g_off[NEXP]) return;
        gbase = m0;
        e = g_tile_expert[t];
    }

    const __half* w1 = g_W1 + (size_t)e * DDIM * IDIM;
    const __half* w2 = g_W2 + (size_t)e * DDIM * IDIM;

    int r0 = tid >> 2, kq = (tid & 3) * 8;
    int r1 = r0 + 64;
    int t0 = routed ? g_pair_token[m0 + r0] : (m0 + r0);
    int t1 = routed ? g_pair_token[m0 + r1] : (m0 + r1);
    uint32_t sz0 = (t0 >= 0) ? 16u : 0u;
    uint32_t sz1 = (t1 >= 0) ? 16u : 0u;
    const __half* a0 = g_X + (size_t)(t0 >= 0 ? t0 : 0) * DDIM + kq;
    const __half* a1 = g_X + (size_t)(t1 >= 0 ? t1 : 0) * DDIM + kq;
    uint32_t dA0 = UG_A + (uint32_t)(r0 * A_STRIDE + kq * 2);
    uint32_t dA1 = UG_A + (uint32_t)(r1 * A_STRIDE + kq * 2);
    int br = tid >> 3, bn = (tid & 7) * 8;
    uint32_t dB = (uint32_t)(br * UG_BSTRIDE + bn * 2);
    size_t bsrc0 = (size_t)br * IDIM + n0 + bn;

    const int NST = DDIM / 32;  // 32

#define UG_ISSUE(s_) do { \
        uint32_t st = sb + (uint32_t)(((s_) % STAGES) * UG_STAGE); \
        int k0 = (s_) * 32; \
        cpa16(st + dA0, a0 + k0, sz0); \
        cpa16(st + dA1, a1 + k0, sz1); \
        size_t bo = bsrc0 + (size_t)k0 * IDIM; \
        cpa16(st + UG_BG + dB, w1 + bo, 16u); \
        cpa16(st + UG_BU + dB, w2 + bo, 16u); \
    } while (0)

    UG_ISSUE(0); CP_COMMIT();
    UG_ISSUE(1); CP_COMMIT();
    UG_ISSUE(2); CP_COMMIT();

    int arow_l = (lane & 7) + ((lane >> 3) & 1) * 8;
    int akc_l = (lane >> 4) * 8;
    int mw = (wid & 3) * 32;
    bool isGate = (wid < 4);
    uint32_t bBase = isGate ? UG_BG : UG_BU;

    float acc[2][8][4];
#pragma unroll
    for (int i = 0; i < 2; i++)
#pragma unroll
        for (int j = 0; j < 8; j++)
#pragma unroll
            for (int q = 0; q < 4; q++) acc[i][j][q] = 0.f;

    for (int s = 0; s < NST; s++) {
        CP_WAIT(2);
        __syncthreads();
        if (s + 3 < NST) UG_ISSUE(s + 3);
        CP_COMMIT();
        uint32_t stg = sb + (uint32_t)((s % STAGES) * UG_STAGE);
#pragma unroll
        for (int ks = 0; ks < 32; ks += 16) {
            uint32_t aF[2][4];
#pragma unroll
            for (int mt = 0; mt < 2; mt++) {
                uint32_t ao = (mw + mt * 16 + arow_l) * A_STRIDE + (ks + akc_l) * 2;
                ldsm_x4(aF[mt], stg + UG_A + ao);
            }
#pragma unroll
            for (int g = 0; g < 4; g++) {
                uint32_t bo = (ks + arow_l) * UG_BSTRIDE + (g * 16 + akc_l) * 2;
                uint32_t bF[4];
                ldsm_x4_t(bF, stg + bBase + bo);
#pragma unroll
                for (int mt = 0; mt < 2; mt++)
#pragma unroll
                    for (int sub = 0; sub < 2; sub++)
                        mma16816(acc[mt][g * 2 + sub], aF[mt], bF + sub * 2);
            }
        }
    }
    CP_WAIT(0);
    __syncthreads();

    float* exch = (float*)smem;
    int fr = lane >> 2, fc = (lane & 3) * 2;
    if (!isGate) {
#pragma unroll
        for (int mt = 0; mt < 2; mt++)
#pragma unroll
            for (int j = 0; j < 8; j++) {
                float* c = acc[mt][j];
                int r = mw + mt * 16 + fr, cl = j * 8 + fc;
                *(float2*)&exch[r * 64 + cl] = make_float2(c[0], c[1]);
                *(float2*)&exch[(r + 8) * 64 + cl] = make_float2(c[2], c[3]);
            }
    }
    __syncthreads();
    if (isGate) {
#pragma unroll
        for (int mt = 0; mt < 2; mt++)
#pragma unroll
            for (int j = 0; j < 8; j++) {
                float* c = acc[mt][j];
                int r = mw + mt * 16 + fr, cl = j * 8 + fc;
                float2 u0 = *(float2*)&exch[r * 64 + cl];
                float2 u1 = *(float2*)&exch[(r + 8) * 64 + cl];
                float2 g0, g1;
                g0.x = c[0] / (1.f + __expf(-c[0])) * u0.x;
                g0.y = c[1] / (1.f + __expf(-c[1])) * u0.y;
                g1.x = c[2] / (1.f + __expf(-c[2])) * u1.x;
                g1.y = c[3] / (1.f + __expf(-c[3])) * u1.y;
                *(float2*)&exch[r * 64 + cl] = g0;
                *(float2*)&exch[(r + 8) * 64 + cl] = g1;
            }
    }
    __syncthreads();
    {
        int r = tid >> 1, cb = (tid & 1) * 32;
        const float4* src = (const float4*)&exch[r * 64 + cb];
        __half* dst = g_Gf + (size_t)(gbase + r) * IDIM + n0 + cb;
#pragma unroll
        for (int j = 0; j < 8; j++) {
            float4 v = src[j];
            __half2 h0 = __floats2half2_rn(v.x, v.y);
            __half2 h1 = __floats2half2_rn(v.z, v.w);
            uint2 o;
            o.x = *reinterpret_cast<uint32_t*>(&h0);
            o.y = *reinterpret_cast<uint32_t*>(&h1);
            ((uint2*)dst)[j] = o;
        }
    }
#undef UG_ISSUE
}

// ---------------- merged down GEMM ----------------
__global__ void __launch_bounds__(256, 2)
down_all(float* __restrict__ out) {
    extern __shared__ char smem[];
    uint32_t sb = smem_u32(smem);
    int tid = threadIdx.x;
    int wid = tid >> 5, lane = tid & 31;
    int by = blockIdx.y, n0 = blockIdx.x * 128;

    bool routed = (by >= NSHARED_TILES);
    int m0, gbase, e;
    if (!routed) { m0 = by * BM; gbase = MAXROWS + m0; e = NEXP; }
    else {
        int t = by - NSHARED_TILES;
        m0 = t * BM;
        if (m0 >= g_off[NEXP]) return;
        gbase = m0;
        e = g_tile_expert[t];
    }

    const __half* w = g_Wd + (size_t)e * IDIM * DDIM;

    int r0 = tid >> 2, kq = (tid & 3) * 8;
    int r1 = r0 + 64;
    const __half* a0 = g_Gf + (size_t)(gbase + r0) * IDIM + kq;
    const __half* a1 = g_Gf + (size_t)(gbase + r1) * IDIM + kq;
    uint32_t dA0 = DN_A + (uint32_t)(r0 * A_STRIDE + kq * 2);
    uint32_t dA1 = DN_A + (uint32_t)(r1 * A_STRIDE + kq * 2);
    int br0 = tid >> 4, bnc = (tid & 15) * 8;
    int br1 = br0 + 16;
    uint32_t dB0 = (uint32_t)(br0 * DN_BSTRIDE + bnc * 2);
    uint32_t dB1 = (uint32_t)(br1 * DN_BSTRIDE + bnc * 2);
    size_t bs0 = (size_t)br0 * DDIM + n0 + bnc;
    size_t bs1 = (size_t)br1 * DDIM + n0 + bnc;

    const int NST = IDIM / 32;  // 64

#define DN_ISSUE(s_) do { \
        uint32_t st = sb + (uint32_t)(((s_) % STAGES) * DN_STAGE); \
        int k0 = (s_) * 32; \
        cpa16(st + dA0, a0 + k0, 16u); \
        cpa16(st + dA1, a1 + k0, 16u); \
        size_t o0 = bs0 + (size_t)k0 * DDIM, o1 = bs1 + (size_t)k0 * DDIM; \
        cpa16(st + DN_B + dB0, w + o0, 16u); \
        cpa16(st + DN_B + dB1, w + o1, 16u); \
    } while (0)

    DN_ISSUE(0); CP_COMMIT();
    DN_ISSUE(1); CP_COMMIT();
    DN_ISSUE(2); CP_COMMIT();

    int arow_l = (lane & 7) + ((lane >> 3) & 1) * 8;
    int akc_l = (lane >> 4) * 8;
    int mw = (wid >> 1) * 32;
    int nwo = (wid & 1) * 64;

    float acc[2][8][4];
#pragma unroll
    for (int i = 0; i < 2; i++)
#pragma unroll
        for (int j = 0; j < 8; j++)
#pragma unroll
            for (int q = 0; q < 4; q++) acc[i][j][q] = 0.f;

    for (int s = 0; s < NST; s++) {
        CP_WAIT(2);
        __syncthreads();
        if (s + 3 < NST) DN_ISSUE(s + 3);
        CP_COMMIT();
        uint32_t stg = sb + (uint32_t)((s % STAGES) * DN_STAGE);
#pragma unroll
        for (int ks = 0; ks < 32; ks += 16) {
            uint32_t aF[2][4];
#pragma unroll
            for (int mt = 0; mt < 2; mt++) {
                uint32_t ao = (mw + mt * 16 + arow_l) * A_STRIDE + (ks + akc_l) * 2;
                ldsm_x4(aF[mt], stg + DN_A + ao);
            }
#pragma unroll
            for (int g = 0; g < 4; g++) {
                uint32_t bo = (ks + arow_l) * DN_BSTRIDE + (nwo + g * 16 + akc_l) * 2;
                uint32_t bF[4];
                ldsm_x4_t(bF, stg + DN_B + bo);
#pragma unroll
                for (int mt = 0; mt < 2; mt++)
#pragma unroll
                    for (int sub = 0; sub < 2; sub++)
                        mma16816(acc[mt][g * 2 + sub], aF[mt], bF + sub * 2);
            }
        }
    }
    CP_WAIT(0);
    __syncthreads();

    float* Cs = (float*)smem;
    int fr = lane >> 2, fc = (lane & 3) * 2;
#pragma unroll
    for (int mt = 0; mt < 2; mt++)
#pragma unroll
        for (int j = 0; j < 8; j++) {
            float* c = acc[mt][j];
            int r = mw + mt * 16 + fr, cl = nwo + j * 8 + fc;
            *(float2*)&Cs[r * 128 + cl] = make_float2(c[0], c[1]);
            *(float2*)&Cs[(r + 8) * 128 + cl] = make_float2(c[2], c[3]);
        }
    __syncthreads();

    int r = tid >> 1, cb = (tid & 1) * 64;
    int tokr = routed ? g_pair_token[m0 + r] : (m0 + r);
    if (tokr >= 0) {
        float wgt = routed ? g_pair_w[m0 + r] : 1.f;
        float* dst = out + (size_t)tokr * DDIM + n0 + cb;
        const float* src = &Cs[r * 128 + cb];
#pragma unroll
        for (int j = 0; j < 16; j++)
            red_add_v4(dst + j * 4, wgt * src[j * 4 + 0], wgt * src[j * 4 + 1],
                       wgt * src[j * 4 + 2], wgt * src[j * 4 + 3]);
    }
#undef DN_ISSUE
}

// ---------------- launch ----------------
extern "C" void kernel_launch(void* const* d_in, const int* in_sizes, int n_in,
                              void* d_out, int out_size) {
    const float* x       = (const float*)d_in[0];
    const float* Wg      = (const float*)d_in[1];
    const float* W_gate  = (const float*)d_in[2];
    const float* W_up    = (const float*)d_in[3];
    const float* W_down  = (const float*)d_in[4];
    const float* Ws_gate = (const float*)d_in[5];
    const float* Ws_up   = (const float*)d_in[6];
    const float* Ws_down = (const float*)d_in[7];
    float* out = (float*)d_out;

    cudaFuncSetAttribute(upgate_all, cudaFuncAttributeMaxDynamicSharedMemorySize, UG_SMEM);
    cudaFuncSetAttribute(down_all,   cudaFuncAttributeMaxDynamicSharedMemorySize, DN_SMEM);

    cudaMemsetAsync(out, 0, (size_t)out_size * sizeof(float));

    prep_kernel<<<NB_PREP, 256>>>(x, Wg, W_gate, Ws_gate, W_up, Ws_up, W_down, Ws_down);
    offsets_kernel<<<1, 256>>>(out, out_size);
    scatter_kernel<<<(NTOK + 255) / 256, 256>>>();

    upgate_all<<<dim3(IDIM / 64, NSHARED_TILES + NTILES), 256, UG_SMEM>>>();
    down_all<<<dim3(DDIM / 128, NSHARED_TILES + NTILES), 256, DN_SMEM>>>(out);
}